// round 5
// baseline (speedup 1.0000x reference)
#include <cuda_runtime.h>

#define N 8192
#define BB 2
#define CH 64
#define KNB 16
#define FULLMASK 0xffffffffu
typedef unsigned long long ull;

// ---------------- scratch (static device globals; no allocation) ----------------
__device__ float g_q1[BB*N*CH];
__device__ float g_q2[BB*N*CH];
__device__ float g_r1[BB*N*CH];
__device__ float g_r2[BB*N*CH];
__device__ float g_f1[BB*N*CH];
__device__ float g_f2[BB*N*CH];
__device__ int   g_i12[BB*N*KNB];
__device__ int   g_i21[BB*N*KNB];

__device__ __forceinline__ float leaky(float x) { return fmaxf(x, 0.1f * x); }

// ---------------- packed f32x2 helpers ----------------
__device__ __forceinline__ ull ffma2(ull a, ull b, ull c) {
    ull d; asm("fma.rn.f32x2 %0, %1, %2, %3;" : "=l"(d) : "l"(a), "l"(b), "l"(c)); return d;
}
__device__ __forceinline__ ull pk2(float x, float y) {
    ull r; asm("mov.b64 %0, {%1, %2};" : "=l"(r) : "f"(x), "f"(y)); return r;
}
__device__ __forceinline__ ull dup2(float x) {
    ull r; asm("mov.b64 %0, {%1, %1};" : "=l"(r) : "f"(x)); return r;
}
__device__ __forceinline__ void unpk2(float& lo, float& hi, ull v) {
    asm("mov.b64 {%0, %1}, %2;" : "=f"(lo), "=f"(hi) : "l"(v));
}
__device__ __forceinline__ ull lky2(ull v) {
    float a, b; unpk2(a, b, v);
    return pk2(fmaxf(a, 0.1f * a), fmaxf(b, 0.1f * b));
}

// ================= fused KNN (z=0,1; 4 queries/warp) + 4-way transform (z=2) =================
#define TILE 4096   // points per smem tile (2048 pairs * 32B = 64KB)

__global__ __launch_bounds__(512) void knn_transform_kernel(
    const float* __restrict__ pc1, const float* __restrict__ pc2,
    int* __restrict__ i12, int* __restrict__ i21,
    const float* __restrict__ f1g, const float* __restrict__ f2g,
    const float* __restrict__ w11, const float* __restrict__ b11,
    const float* __restrict__ w22, const float* __restrict__ b22,
    float* __restrict__ q1o, float* __restrict__ q2o,
    float* __restrict__ r1o, float* __restrict__ r2o)
{
    extern __shared__ char smraw[];
    const int tid = threadIdx.x;

    if (blockIdx.z == 2) {
        // ---- 4-way feature transform: 16 points per block ----
        ull* s_wp  = (ull*)smraw;       // 4096: [c][m] = (w11[m][c], w22[m][c])
        ull* s_f12 = s_wp + 4096;       // 1024: [c][np] = (f1, f2)
        ull* s_f21 = s_f12 + 1024;      // 1024: [c][np] = (f2, f1)
        const int b = blockIdx.y, n0 = blockIdx.x * 16;
        for (int i = tid; i < 4096; i += 512) {
            int m = i >> 6, c = i & 63;
            s_wp[c * 64 + m] = pk2(w11[i], w22[i]);
        }
        for (int i = tid; i < 1024; i += 512) {
            int c = i >> 4, np = i & 15;
            float a = f1g[(b * 64 + c) * N + n0 + np];
            float d = f2g[(b * 64 + c) * N + n0 + np];
            s_f12[i] = pk2(a, d);
            s_f21[i] = pk2(d, a);
        }
        __syncthreads();
        const int m = tid & 63, grp = tid >> 6;  // grp 0..7, 2 points each
        ull bq = pk2(b11[m], b22[m]);
        ull a0 = bq, a1 = bq, r0 = bq, r1v = bq;
        const int np = grp * 2;
        #pragma unroll 8
        for (int c = 0; c < 64; c++) {
            ull wv = s_wp[c * 64 + m];
            a0  = ffma2(s_f12[c * 16 + np],     wv, a0);
            a1  = ffma2(s_f12[c * 16 + np + 1], wv, a1);
            r0  = ffma2(s_f21[c * 16 + np],     wv, r0);
            r1v = ffma2(s_f21[c * 16 + np + 1], wv, r1v);
        }
        float v1, v2;
        int q = (b * N + n0 + np) * 64 + m;
        unpk2(v1, v2, a0);  q1o[q] = v1;      q2o[q] = v2;
        unpk2(v1, v2, a1);  q1o[q + 64] = v1; q2o[q + 64] = v2;
        unpk2(v1, v2, r0);  r1o[q] = v1;      r2o[q] = v2;
        unpk2(v1, v2, r1v); r1o[q + 64] = v1; r2o[q + 64] = v2;
        return;
    }

    // ---- KNN: 4 queries per warp; 2 register sets x 2 half-warp top-16 lists ----
    if (blockIdx.x >= N / 64) return;
    ulonglong2* s_t0 = (ulonglong2*)smraw;     // 2048: (x-pair, y-pair)
    ulonglong2* s_t1 = s_t0 + (TILE / 2);      // 2048: (z-pair, |p|^2-pair)
    const int dir = blockIdx.z;
    const float* q  = dir ? pc2 : pc1;
    const float* db = dir ? pc1 : pc2;
    int* oi = dir ? i21 : i12;
    const int b = blockIdx.y;
    const int warp = tid >> 5, lane = tid & 31;
    const int n0 = blockIdx.x * 64 + warp * 4;
    const float* qb = q + b * 3 * N;
    ull m2x[4], m2y[4], m2z[4];
    #pragma unroll
    for (int u = 0; u < 4; u++) {
        m2x[u] = dup2(-2.0f * qb[n0 + u]);
        m2y[u] = dup2(-2.0f * qb[N + n0 + u]);
        m2z[u] = dup2(-2.0f * qb[2 * N + n0 + u]);
    }
    const float* dbb = db + b * 3 * N;

    // list set 1: queries n0 (lanes 0-15), n0+1 (lanes 16-31)
    // list set 2: queries n0+2 (lanes 0-15), n0+3 (lanes 16-31)
    float bd1 = 3.0e38f, bd2 = 3.0e38f;
    int bi1 = 0, bi2 = 0;
    float tau0 = 3.0e38f, tau1 = 3.0e38f, tau2 = 3.0e38f, tau3 = 3.0e38f;
    const bool halfA = (lane < 16);

    for (int t = 0; t < N; t += TILE) {
        __syncthreads();
        const float2* gx = (const float2*)(dbb + t);
        const float2* gy = (const float2*)(dbb + N + t);
        const float2* gz = (const float2*)(dbb + 2 * N + t);
        for (int i = tid; i < TILE / 2; i += 512) {
            float2 x = gx[i], y = gy[i], z = gz[i];
            float w0 = x.x * x.x + y.x * y.x + z.x * z.x;
            float w1 = x.y * x.y + y.y * y.y + z.y * z.y;
            ulonglong2 A, B;
            A.x = *(const ull*)&x; A.y = *(const ull*)&y;
            B.x = *(const ull*)&z; B.y = pk2(w0, w1);
            s_t0[i] = A; s_t1[i] = B;
        }
        __syncthreads();
        #pragma unroll 2
        for (int p = 0; p < TILE / 2; p += 32) {
            ulonglong2 t0 = s_t0[p + lane];
            ulonglong2 t1 = s_t1[p + lane];
            float d0[4], d1[4];
            #pragma unroll
            for (int u = 0; u < 4; u++) {
                ull dv = ffma2(t0.x, m2x[u], t1.y);
                dv = ffma2(t0.y, m2y[u], dv);
                dv = ffma2(t1.x, m2z[u], dv);
                unpk2(d0[u], d1[u], dv);
            }
            bool hit = (fminf(d0[0], d1[0]) < tau0) | (fminf(d0[1], d1[1]) < tau1)
                     | (fminf(d0[2], d1[2]) < tau2) | (fminf(d0[3], d1[3]) < tau3);
            if (__ballot_sync(FULLMASK, hit)) {
                const int base = t + 2 * p;
                #pragma unroll
                for (int e = 0; e < 2; e++) {
                    float v0 = e ? d1[0] : d0[0];
                    float v1 = e ? d1[1] : d0[1];
                    float v2 = e ? d1[2] : d0[2];
                    float v3 = e ? d1[3] : d0[3];
                    unsigned q0m = __ballot_sync(FULLMASK, v0 < tau0);
                    unsigned q1m = __ballot_sync(FULLMASK, v1 < tau1);
                    unsigned q2m = __ballot_sync(FULLMASK, v2 < tau2);
                    unsigned q3m = __ballot_sync(FULLMASK, v3 < tau3);
                    if (!(q0m | q1m | q2m | q3m)) continue;
                    unsigned mm1 = halfA ? q0m : q1m;
                    unsigned mm2 = halfA ? q2m : q3m;
                    int nit = max(max(__popc(q0m), __popc(q1m)),
                                  max(__popc(q2m), __popc(q3m)));
                    for (int it = 0; it < nit; it++) {
                        int s1 = __ffs(mm1) - 1;
                        int s2 = __ffs(mm2) - 1;
                        float a1v = __shfl_sync(FULLMASK, v0, s1 & 31);
                        float b1v = __shfl_sync(FULLMASK, v1, s1 & 31);
                        float dd1 = halfA ? a1v : b1v;
                        float a2v = __shfl_sync(FULLMASK, v2, s2 & 31);
                        float b2v = __shfl_sync(FULLMASK, v3, s2 & 31);
                        float dd2 = halfA ? a2v : b2v;
                        float up1 = __shfl_up_sync(FULLMASK, bd1, 1, 16);
                        int  upi1 = __shfl_up_sync(FULLMASK, bi1, 1, 16);
                        float up2 = __shfl_up_sync(FULLMASK, bd2, 1, 16);
                        int  upi2 = __shfl_up_sync(FULLMASK, bi2, 1, 16);
                        if ((lane & 15) == 0) { up1 = -3.0e38f; up2 = -3.0e38f; }
                        if (mm1 && bd1 > dd1) {
                            bool tk = up1 > dd1;
                            bd1 = tk ? up1 : dd1;
                            bi1 = tk ? upi1 : base + 2 * s1 + e;
                        }
                        if (mm2 && bd2 > dd2) {
                            bool tk = up2 > dd2;
                            bd2 = tk ? up2 : dd2;
                            bi2 = tk ? upi2 : base + 2 * s2 + e;
                        }
                        mm1 &= mm1 - 1;
                        mm2 &= mm2 - 1;
                    }
                }
                tau0 = __shfl_sync(FULLMASK, bd1, 15);
                tau1 = __shfl_sync(FULLMASK, bd1, 31);
                tau2 = __shfl_sync(FULLMASK, bd2, 15);
                tau3 = __shfl_sync(FULLMASK, bd2, 31);
            }
        }
    }
    const int nOut1 = n0 + (halfA ? 0 : 1);
    const int nOut2 = n0 + (halfA ? 2 : 3);
    oi[((b * N) + nOut1) * 16 + (lane & 15)] = bi1;
    oi[((b * N) + nOut2) * 16 + (lane & 15)] = bi2;
}

// ================= fused cross (+ optional final-linear epilogue) =================
// smem float offsets
#define OW1 0
#define OW2 4096
#define OW3 8192
#define OPWT 12288
#define OPB  12480
#define OB1  12544
#define OB2  12608
#define OB3  12672
#define OHP  12736                 // ull region: 8 warps * 512 = 4096 ull
#define OST  (12736 + 4096*2)      // float offset of stash: 8 warps * 256 ull
#define SMEM_FLOATS (12736 + 4096*2 + 2048*2)

template <int NL, int EPI>
__global__ __launch_bounds__(256) void cross_kernel(
    const int* __restrict__ iA, const int* __restrict__ iB,
    const float* __restrict__ xA, const float* __restrict__ xB,
    const float* __restrict__ p1A, const float* __restrict__ p2A,
    const float* __restrict__ p1B, const float* __restrict__ p2B,
    const float* __restrict__ posw, const float* __restrict__ posb,
    const float* __restrict__ w1, const float* __restrict__ b1,
    const float* __restrict__ w2, const float* __restrict__ b2,
    const float* __restrict__ w3A, const float* __restrict__ b3A,
    const float* __restrict__ w3B, const float* __restrict__ b3B,
    float* __restrict__ obnA, float* __restrict__ obnB,
    float* __restrict__ ocnA, float* __restrict__ ocnB)
{
    extern __shared__ float sm[];
    float* s_w1  = sm + OW1;
    float* s_w2  = sm + OW2;
    float* s_w3  = sm + OW3;
    float* s_pwt = sm + OPWT;
    float* s_pb  = sm + OPB;
    float* s_b1  = sm + OB1;
    float* s_b2  = sm + OB2;
    float* s_b3  = sm + OB3;
    ull*   s_hp  = (ull*)(sm + OHP);
    ull*   s_st  = (ull*)(sm + OST);

    const int dir = blockIdx.y;
    const int* idx = dir ? iB : iA;
    const float* xyz1 = dir ? xB : xA;
    const float* xyz2 = dir ? xA : xB;
    const float* p1 = dir ? p1B : p1A;
    const float* p2 = dir ? p2B : p2A;
    const float* w3 = dir ? w3B : w3A;
    const float* b3 = dir ? b3B : b3A;
    float* obn = dir ? obnB : obnA;
    float* ocn = dir ? ocnB : ocnA;

    const int tid = threadIdx.x;
    for (int i = tid; i < 4096; i += 256) {
        int jb = i >> 8, c = (i >> 2) & 63, u = i & 3;
        s_w1[i] = w1[c * 64 + jb * 4 + u];
        if (NL == 2) s_w2[i] = w2[c * 64 + jb * 4 + u];
        if (EPI)     s_w3[i] = w3[c * 64 + jb * 4 + u];
    }
    if (tid < 192) s_pwt[tid] = posw[(tid & 63) * 3 + (tid >> 6)];
    if (tid < 64) {
        s_pb[tid] = posb[tid];
        s_b1[tid] = b1[tid];
        if (NL == 2) s_b2[tid] = b2[tid];
        if (EPI)     s_b3[tid] = b3[tid];
    }
    __syncthreads();

    const int warp = tid >> 5, lane = tid & 31;
    ull* shp = s_hp + warp * 512;
    ull* sst = s_st + warp * 256;
    const int wq0 = (blockIdx.x * 8 + warp) * 8;

    const float pw0a = s_pwt[lane],      pw1a = s_pwt[64 + lane],  pw2a = s_pwt[128 + lane];
    const float pw0b = s_pwt[lane + 32], pw1b = s_pwt[96 + lane],  pw2b = s_pwt[160 + lane];
    const float pba = s_pb[lane], pbb = s_pb[lane + 32];
    const ull bd1a = dup2(s_b1[lane]), bd1b = dup2(s_b1[lane + 32]);
    const ull bd2a = (NL == 2) ? dup2(s_b2[lane]) : 0ull;
    const ull bd2b = (NL == 2) ? dup2(s_b2[lane + 32]) : 0ull;

    float pma = 0.f, pmb = 0.f;

    for (int qi = 0; qi < 8; qi++) {
        const int q = wq0 + qi;
        const int b = q >> 13, n = q & (N - 1);
        const int myidx = idx[q * 16 + (lane & 15)];
        const float p1a = p1[q * 64 + lane];
        const float p1b = p1[q * 64 + 32 + lane];
        const float* x1b = xyz1 + b * 3 * N;
        const float qx = x1b[n], qy = x1b[N + n], qz = x1b[2 * N + n];
        const float* x2b = xyz2 + b * 3 * N;
        const float nx = x2b[myidx], ny = x2b[N + myidx], nz = x2b[2 * N + myidx];

        float pva = 0.f, pvb = 0.f;
        #pragma unroll
        for (int k = 0; k < 16; k++) {
            int j = __shfl_sync(FULLMASK, myidx, k);
            float dx = __shfl_sync(FULLMASK, nx, k) - qx;
            float dy = __shfl_sync(FULLMASK, ny, k) - qy;
            float dz = __shfl_sync(FULLMASK, nz, k) - qz;
            const float* p2r = p2 + ((size_t)((b << 13) + j)) * 64;
            float ga = p2r[lane], gb = p2r[lane + 32];
            float pa = pba + dx * pw0a + dy * pw1a + dz * pw2a;
            float pb = pbb + dx * pw0b + dy * pw1b + dz * pw2b;
            float ha = leaky(ga + p1a + pa);
            float hb = leaky(gb + p1b + pb);
            if (k & 1) {
                shp[(k >> 1) * 64 + lane]      = pk2(pva, ha);
                shp[(k >> 1) * 64 + lane + 32] = pk2(pvb, hb);
            } else { pva = ha; pvb = hb; }
        }
        __syncwarp();

        ull ya[8], yb[8];
        #pragma unroll
        for (int k2 = 0; k2 < 8; k2++) { ya[k2] = bd1a; yb[k2] = bd1b; }
        #pragma unroll
        for (int jb = 0; jb < 16; jb++) {
            float4 wa = *(const float4*)(s_w1 + (jb * 64 + lane) * 4);
            float4 wb = *(const float4*)(s_w1 + (jb * 64 + lane + 32) * 4);
            ull wax = dup2(wa.x), way = dup2(wa.y), waz = dup2(wa.z), waw = dup2(wa.w);
            ull wbx = dup2(wb.x), wby = dup2(wb.y), wbz = dup2(wb.z), wbw = dup2(wb.w);
            #pragma unroll
            for (int k2 = 0; k2 < 8; k2++) {
                ulonglong2 h01 = *(const ulonglong2*)(shp + k2 * 64 + jb * 4);
                ulonglong2 h23 = *(const ulonglong2*)(shp + k2 * 64 + jb * 4 + 2);
                ya[k2] = ffma2(h01.x, wax, ya[k2]);
                yb[k2] = ffma2(h01.x, wbx, yb[k2]);
                ya[k2] = ffma2(h01.y, way, ya[k2]);
                yb[k2] = ffma2(h01.y, wby, yb[k2]);
                ya[k2] = ffma2(h23.x, waz, ya[k2]);
                yb[k2] = ffma2(h23.x, wbz, yb[k2]);
                ya[k2] = ffma2(h23.y, waw, ya[k2]);
                yb[k2] = ffma2(h23.y, wbw, yb[k2]);
            }
        }

        if (NL == 2) {
            __syncwarp();
            #pragma unroll
            for (int k2 = 0; k2 < 8; k2++) {
                shp[k2 * 64 + lane]      = lky2(ya[k2]);
                shp[k2 * 64 + lane + 32] = lky2(yb[k2]);
            }
            __syncwarp();
            #pragma unroll
            for (int k2 = 0; k2 < 8; k2++) { ya[k2] = bd2a; yb[k2] = bd2b; }
            #pragma unroll
            for (int jb = 0; jb < 16; jb++) {
                float4 wa = *(const float4*)(s_w2 + (jb * 64 + lane) * 4);
                float4 wb = *(const float4*)(s_w2 + (jb * 64 + lane + 32) * 4);
                ull wax = dup2(wa.x), way = dup2(wa.y), waz = dup2(wa.z), waw = dup2(wa.w);
                ull wbx = dup2(wb.x), wby = dup2(wb.y), wbz = dup2(wb.z), wbw = dup2(wb.w);
                #pragma unroll
                for (int k2 = 0; k2 < 8; k2++) {
                    ulonglong2 h01 = *(const ulonglong2*)(shp + k2 * 64 + jb * 4);
                    ulonglong2 h23 = *(const ulonglong2*)(shp + k2 * 64 + jb * 4 + 2);
                    ya[k2] = ffma2(h01.x, wax, ya[k2]);
                    yb[k2] = ffma2(h01.x, wbx, yb[k2]);
                    ya[k2] = ffma2(h01.y, way, ya[k2]);
                    yb[k2] = ffma2(h01.y, wby, yb[k2]);
                    ya[k2] = ffma2(h23.x, waz, ya[k2]);
                    yb[k2] = ffma2(h23.x, wbz, yb[k2]);
                    ya[k2] = ffma2(h23.y, waw, ya[k2]);
                    yb[k2] = ffma2(h23.y, wbw, yb[k2]);
                }
            }
        }

        float ma = -3.0e38f, mb = -3.0e38f;
        #pragma unroll
        for (int k2 = 0; k2 < 8; k2++) {
            float u, v;
            unpk2(u, v, ya[k2]); ma = fmaxf(ma, fmaxf(u, v));
            unpk2(u, v, yb[k2]); mb = fmaxf(mb, fmaxf(u, v));
        }
        ma = leaky(ma); mb = leaky(mb);

        if (EPI) {
            if (qi & 1) {
                sst[(qi >> 1) * 64 + lane]      = pk2(pma, ma);
                sst[(qi >> 1) * 64 + 32 + lane] = pk2(pmb, mb);
            } else { pma = ma; pmb = mb; }
        } else {
            // transposed direct write (cross3)
            ocn[((b * 64) + lane) * N + n] = ma;
            ocn[((b * 64) + lane + 32) * N + n] = mb;
        }
        __syncwarp();
    }

    if (EPI) {
        __syncwarp();
        ull za[4], zb[4];
        const ull bd3a = dup2(s_b3[lane]), bd3b = dup2(s_b3[lane + 32]);
        #pragma unroll
        for (int q2 = 0; q2 < 4; q2++) { za[q2] = bd3a; zb[q2] = bd3b; }
        #pragma unroll
        for (int jb = 0; jb < 16; jb++) {
            float4 wa = *(const float4*)(s_w3 + (jb * 64 + lane) * 4);
            float4 wb = *(const float4*)(s_w3 + (jb * 64 + lane + 32) * 4);
            ull wax = dup2(wa.x), way = dup2(wa.y), waz = dup2(wa.z), waw = dup2(wa.w);
            ull wbx = dup2(wb.x), wby = dup2(wb.y), wbz = dup2(wb.z), wbw = dup2(wb.w);
            #pragma unroll
            for (int q2 = 0; q2 < 4; q2++) {
                ulonglong2 h01 = *(const ulonglong2*)(sst + q2 * 64 + jb * 4);
                ulonglong2 h23 = *(const ulonglong2*)(sst + q2 * 64 + jb * 4 + 2);
                za[q2] = ffma2(h01.x, wax, za[q2]);
                zb[q2] = ffma2(h01.x, wbx, zb[q2]);
                za[q2] = ffma2(h01.y, way, za[q2]);
                zb[q2] = ffma2(h01.y, wby, zb[q2]);
                za[q2] = ffma2(h23.x, waz, za[q2]);
                zb[q2] = ffma2(h23.x, wbz, zb[q2]);
                za[q2] = ffma2(h23.y, waw, za[q2]);
                zb[q2] = ffma2(h23.y, wbw, zb[q2]);
            }
        }
        #pragma unroll
        for (int q2 = 0; q2 < 4; q2++) {
            const int q = wq0 + 2 * q2;
            const int b = q >> 13, n = q & (N - 1);
            float lo, hi;
            unpk2(lo, hi, za[q2]);
            obn[q * 64 + lane] = lo;
            obn[(q + 1) * 64 + lane] = hi;
            *(float2*)&ocn[((b * 64) + lane) * N + n] = make_float2(lo, hi);
            unpk2(lo, hi, zb[q2]);
            obn[q * 64 + 32 + lane] = lo;
            obn[(q + 1) * 64 + 32 + lane] = hi;
            *(float2*)&ocn[((b * 64) + lane + 32) * N + n] = make_float2(lo, hi);
        }
    }
}

// ---------------- launch ----------------
extern "C" void kernel_launch(void* const* d_in, const int* in_sizes, int n_in,
                              void* d_out, int out_size)
{
    const float* pc1     = (const float*)d_in[0];
    const float* pc2     = (const float*)d_in[1];
    const float* feat1   = (const float*)d_in[2];
    const float* feat2   = (const float*)d_in[3];
    const float* t11_w   = (const float*)d_in[4];
    const float* t11_b   = (const float*)d_in[5];
    const float* t22_w   = (const float*)d_in[6];
    const float* t22_b   = (const float*)d_in[7];
    const float* pos1_w  = (const float*)d_in[8];
    const float* pos1_b  = (const float*)d_in[9];
    const float* mlp1_w1 = (const float*)d_in[10];
    const float* mlp1_b1 = (const float*)d_in[11];
    const float* mlp1_w2 = (const float*)d_in[12];
    const float* mlp1_b2 = (const float*)d_in[13];
    const float* t1_w    = (const float*)d_in[14];
    const float* t1_b    = (const float*)d_in[15];
    const float* t2_w    = (const float*)d_in[16];
    const float* t2_b    = (const float*)d_in[17];
    const float* pos2_w  = (const float*)d_in[18];
    const float* pos2_b  = (const float*)d_in[19];
    const float* mlp2_w1 = (const float*)d_in[20];
    const float* mlp2_b1 = (const float*)d_in[21];
    float* out = (float*)d_out;

    float *q1, *q2, *r1, *r2, *f1, *f2;
    int *i12, *i21;
    cudaGetSymbolAddress((void**)&q1, g_q1);
    cudaGetSymbolAddress((void**)&q2, g_q2);
    cudaGetSymbolAddress((void**)&r1, g_r1);
    cudaGetSymbolAddress((void**)&r2, g_r2);
    cudaGetSymbolAddress((void**)&f1, g_f1);
    cudaGetSymbolAddress((void**)&f2, g_f2);
    cudaGetSymbolAddress((void**)&i12, g_i12);
    cudaGetSymbolAddress((void**)&i21, g_i21);

    // fused KNN (z=0,1; grid.x<128 active) + transforms (z=2; grid.x<512 active)
    const size_t smem_kt = (size_t)TILE / 2 * 32;   // 64KB
    cudaFuncSetAttribute(knn_transform_kernel, cudaFuncAttributeMaxDynamicSharedMemorySize, (int)smem_kt);
    knn_transform_kernel<<<dim3(N / 16, BB, 3), 512, smem_kt>>>(
        pc1, pc2, i12, i21,
        feat1, feat2, t11_w, t11_b, t22_w, t22_b,
        q1, q2, r1, r2);

    const size_t smem = (size_t)SMEM_FLOATS * sizeof(float);
    cudaFuncSetAttribute(cross_kernel<2,1>, cudaFuncAttributeMaxDynamicSharedMemorySize, (int)smem);
    cudaFuncSetAttribute(cross_kernel<1,0>, cudaFuncAttributeMaxDynamicSharedMemorySize, (int)smem);

    // cross 1 & 2 fused (grid.y = direction) with final-linear epilogue
    cross_kernel<2,1><<<dim3(BB * N / 64, 2), 256, smem>>>(
        i12, i21, pc1, pc2,
        q1, q2, r1, r2,
        pos1_w, pos1_b, mlp1_w1, mlp1_b1, mlp1_w2, mlp1_b2,
        t1_w, t1_b, t2_w, t2_b,
        f1, f2, out, out + (size_t)BB * 64 * N);

    // cross 3 (1 mlp layer), transposed direct write to output region 2
    cross_kernel<1,0><<<dim3(BB * N / 64, 1), 256, smem>>>(
        i12, i12, pc1, pc2,
        f1, f2, f1, f2,
        pos2_w, pos2_b, mlp2_w1, mlp2_b1, mlp2_w1, mlp2_b1,
        mlp2_w1, mlp2_b1, mlp2_w1, mlp2_b1,
        out + (size_t)2 * BB * 64 * N, out + (size_t)2 * BB * 64 * N,
        out + (size_t)2 * BB * 64 * N, out + (size_t)2 * BB * 64 * N);
}

// round 6
// speedup vs baseline: 1.0382x; 1.0382x over previous
#include <cuda_runtime.h>

#define N 8192
#define BB 2
#define CH 64
#define KNB 16
#define FULLMASK 0xffffffffu
typedef unsigned long long ull;

// ---------------- scratch (static device globals; no allocation) ----------------
__device__ float g_q1[BB*N*CH];
__device__ float g_q2[BB*N*CH];
__device__ float g_r1[BB*N*CH];
__device__ float g_r2[BB*N*CH];
__device__ float g_f1[BB*N*CH];
__device__ float g_f2[BB*N*CH];
__device__ int   g_i12[BB*N*KNB];
__device__ int   g_i21[BB*N*KNB];

__device__ __forceinline__ float leaky(float x) { return fmaxf(x, 0.1f * x); }

// ---------------- packed f32x2 helpers ----------------
__device__ __forceinline__ ull ffma2(ull a, ull b, ull c) {
    ull d; asm("fma.rn.f32x2 %0, %1, %2, %3;" : "=l"(d) : "l"(a), "l"(b), "l"(c)); return d;
}
__device__ __forceinline__ ull pk2(float x, float y) {
    ull r; asm("mov.b64 %0, {%1, %2};" : "=l"(r) : "f"(x), "f"(y)); return r;
}
__device__ __forceinline__ ull dup2(float x) {
    ull r; asm("mov.b64 %0, {%1, %1};" : "=l"(r) : "f"(x)); return r;
}
__device__ __forceinline__ void unpk2(float& lo, float& hi, ull v) {
    asm("mov.b64 {%0, %1}, %2;" : "=f"(lo), "=f"(hi) : "l"(v));
}
__device__ __forceinline__ ull lky2(ull v) {
    float a, b; unpk2(a, b, v);
    return pk2(fmaxf(a, 0.1f * a), fmaxf(b, 0.1f * b));
}

// ================= fused KNN (z=0,1; 2 queries/warp) + 4-way transform (z=2) =================
#define TILE 4096   // points per smem tile (2048 pairs * 32B = 64KB)

__global__ __launch_bounds__(512, 3) void knn_transform_kernel(
    const float* __restrict__ pc1, const float* __restrict__ pc2,
    int* __restrict__ i12, int* __restrict__ i21,
    const float* __restrict__ f1g, const float* __restrict__ f2g,
    const float* __restrict__ w11, const float* __restrict__ b11,
    const float* __restrict__ w22, const float* __restrict__ b22,
    float* __restrict__ q1o, float* __restrict__ q2o,
    float* __restrict__ r1o, float* __restrict__ r2o)
{
    extern __shared__ char smraw[];
    const int tid = threadIdx.x;

    if (blockIdx.z == 2) {
        // ---- 4-way feature transform: 16 points per block ----
        ull* s_wp  = (ull*)smraw;       // 4096: [c][m] = (w11[m][c], w22[m][c])
        ull* s_f12 = s_wp + 4096;       // 1024: [c][np] = (f1, f2)
        ull* s_f21 = s_f12 + 1024;      // 1024: [c][np] = (f2, f1)
        const int b = blockIdx.y, n0 = blockIdx.x * 16;
        for (int i = tid; i < 4096; i += 512) {
            int m = i >> 6, c = i & 63;
            s_wp[c * 64 + m] = pk2(w11[i], w22[i]);
        }
        for (int i = tid; i < 1024; i += 512) {
            int c = i >> 4, np = i & 15;
            float a = f1g[(b * 64 + c) * N + n0 + np];
            float d = f2g[(b * 64 + c) * N + n0 + np];
            s_f12[i] = pk2(a, d);
            s_f21[i] = pk2(d, a);
        }
        __syncthreads();
        const int m = tid & 63, grp = tid >> 6;  // grp 0..7, 2 points each
        ull bq = pk2(b11[m], b22[m]);
        ull a0 = bq, a1 = bq, r0 = bq, r1v = bq;
        const int np = grp * 2;
        #pragma unroll 8
        for (int c = 0; c < 64; c++) {
            ull wv = s_wp[c * 64 + m];
            a0  = ffma2(s_f12[c * 16 + np],     wv, a0);
            a1  = ffma2(s_f12[c * 16 + np + 1], wv, a1);
            r0  = ffma2(s_f21[c * 16 + np],     wv, r0);
            r1v = ffma2(s_f21[c * 16 + np + 1], wv, r1v);
        }
        float v1, v2;
        int q = (b * N + n0 + np) * 64 + m;
        unpk2(v1, v2, a0);  q1o[q] = v1;      q2o[q] = v2;
        unpk2(v1, v2, a1);  q1o[q + 64] = v1; q2o[q + 64] = v2;
        unpk2(v1, v2, r0);  r1o[q] = v1;      r2o[q] = v2;
        unpk2(v1, v2, r1v); r1o[q + 64] = v1; r2o[q + 64] = v2;
        return;
    }

    // ---- KNN: 2 queries per warp, top-16 list per 16-lane half, 128 candidates/iter ----
    if (blockIdx.x >= N / 32) return;
    ulonglong2* s_t0 = (ulonglong2*)smraw;     // 2048: (x-pair, y-pair)
    ulonglong2* s_t1 = s_t0 + (TILE / 2);      // 2048: (z-pair, |p|^2-pair)
    const int dir = blockIdx.z;
    const float* q  = dir ? pc2 : pc1;
    const float* db = dir ? pc1 : pc2;
    int* oi = dir ? i21 : i12;
    const int b = blockIdx.y;
    const int warp = tid >> 5, lane = tid & 31;
    const int nA = blockIdx.x * 32 + warp * 2;
    const int nB = nA + 1;
    const float* qb = q + b * 3 * N;
    const ull m2qAx = dup2(-2.0f * qb[nA]);
    const ull m2qAy = dup2(-2.0f * qb[N + nA]);
    const ull m2qAz = dup2(-2.0f * qb[2 * N + nA]);
    const ull m2qBx = dup2(-2.0f * qb[nB]);
    const ull m2qBy = dup2(-2.0f * qb[N + nB]);
    const ull m2qBz = dup2(-2.0f * qb[2 * N + nB]);
    const float* dbb = db + b * 3 * N;

    float bd = 3.0e38f;   // sorted ascending within each 16-lane half
    int bi = 0;
    float tauA = 3.0e38f, tauB = 3.0e38f;
    const bool halfA = (lane < 16);

    for (int t = 0; t < N; t += TILE) {
        __syncthreads();
        const float2* gx = (const float2*)(dbb + t);
        const float2* gy = (const float2*)(dbb + N + t);
        const float2* gz = (const float2*)(dbb + 2 * N + t);
        for (int i = tid; i < TILE / 2; i += 512) {
            float2 x = gx[i], y = gy[i], z = gz[i];
            float w0 = x.x * x.x + y.x * y.x + z.x * z.x;
            float w1 = x.y * x.y + y.y * y.y + z.y * z.y;
            ulonglong2 A, B;
            A.x = *(const ull*)&x; A.y = *(const ull*)&y;
            B.x = *(const ull*)&z; B.y = pk2(w0, w1);
            s_t0[i] = A; s_t1[i] = B;
        }
        __syncthreads();
        for (int p = 0; p < TILE / 2; p += 64) {
            ulonglong2 t0a = s_t0[p + lane];
            ulonglong2 t1a = s_t1[p + lane];
            ulonglong2 t0b = s_t0[p + 32 + lane];
            ulonglong2 t1b = s_t1[p + 32 + lane];
            float fA[4], fB[4];
            ull dv;
            dv = ffma2(t0a.x, m2qAx, t1a.y); dv = ffma2(t0a.y, m2qAy, dv); dv = ffma2(t1a.x, m2qAz, dv);
            unpk2(fA[0], fA[1], dv);
            dv = ffma2(t0b.x, m2qAx, t1b.y); dv = ffma2(t0b.y, m2qAy, dv); dv = ffma2(t1b.x, m2qAz, dv);
            unpk2(fA[2], fA[3], dv);
            dv = ffma2(t0a.x, m2qBx, t1a.y); dv = ffma2(t0a.y, m2qBy, dv); dv = ffma2(t1a.x, m2qBz, dv);
            unpk2(fB[0], fB[1], dv);
            dv = ffma2(t0b.x, m2qBx, t1b.y); dv = ffma2(t0b.y, m2qBy, dv); dv = ffma2(t1b.x, m2qBz, dv);
            unpk2(fB[2], fB[3], dv);
            float mnA = fminf(fminf(fA[0], fA[1]), fminf(fA[2], fA[3]));
            float mnB = fminf(fminf(fB[0], fB[1]), fminf(fB[2], fB[3]));
            if (__ballot_sync(FULLMASK, (mnA < tauA) | (mnB < tauB))) {
                #pragma unroll
                for (int ph = 0; ph < 4; ph++) {
                    float vA = fA[ph], vB = fB[ph];
                    unsigned mA = __ballot_sync(FULLMASK, vA < tauA);
                    unsigned mB = __ballot_sync(FULLMASK, vB < tauB);
                    if (!(mA | mB)) continue;
                    unsigned mm = halfA ? mA : mB;
                    int nit = max(__popc(mA), __popc(mB));
                    for (int it = 0; it < nit; it++) {
                        int src = __ffs(mm) - 1;
                        float v1 = __shfl_sync(FULLMASK, vA, src & 31);
                        float v2 = __shfl_sync(FULLMASK, vB, src & 31);
                        float dd = halfA ? v1 : v2;
                        float up  = __shfl_up_sync(FULLMASK, bd, 1, 16);
                        int   upi = __shfl_up_sync(FULLMASK, bi, 1, 16);
                        if ((lane & 15) == 0) up = -3.0e38f;
                        if (mm && bd > dd) {
                            bool tk = up > dd;
                            bd = tk ? up : dd;
                            bi = tk ? upi : t + 2 * (p + (ph >> 1) * 32 + src) + (ph & 1);
                        }
                        mm &= mm - 1;
                    }
                }
                tauA = __shfl_sync(FULLMASK, bd, 15);
                tauB = __shfl_sync(FULLMASK, bd, 31);
            }
        }
    }
    const int nOut = halfA ? nA : nB;
    oi[((b * N) + nOut) * 16 + (lane & 15)] = bi;
}

// ================= fused cross (+ optional final-linear epilogue) =================
// smem float offsets
#define OW1 0
#define OW2 4096
#define OW3 8192
#define OPWT 12288
#define OPB  12480
#define OB1  12544
#define OB2  12608
#define OB3  12672
#define OHP  12736                 // ull region: 8 warps * 512 = 4096 ull
#define OST  (12736 + 4096*2)      // float offset of stash: 8 warps * 256 ull
#define SMEM_FLOATS (12736 + 4096*2 + 2048*2)

template <int NL, int EPI>
__global__ __launch_bounds__(256) void cross_kernel(
    const int* __restrict__ iA, const int* __restrict__ iB,
    const float* __restrict__ xA, const float* __restrict__ xB,
    const float* __restrict__ p1A, const float* __restrict__ p2A,
    const float* __restrict__ p1B, const float* __restrict__ p2B,
    const float* __restrict__ posw, const float* __restrict__ posb,
    const float* __restrict__ w1, const float* __restrict__ b1,
    const float* __restrict__ w2, const float* __restrict__ b2,
    const float* __restrict__ w3A, const float* __restrict__ b3A,
    const float* __restrict__ w3B, const float* __restrict__ b3B,
    float* __restrict__ obnA, float* __restrict__ obnB,
    float* __restrict__ ocnA, float* __restrict__ ocnB)
{
    extern __shared__ float sm[];
    float* s_w1  = sm + OW1;
    float* s_w2  = sm + OW2;
    float* s_w3  = sm + OW3;
    float* s_pwt = sm + OPWT;
    float* s_pb  = sm + OPB;
    float* s_b1  = sm + OB1;
    float* s_b2  = sm + OB2;
    float* s_b3  = sm + OB3;
    ull*   s_hp  = (ull*)(sm + OHP);
    ull*   s_st  = (ull*)(sm + OST);

    const int dir = blockIdx.y;
    const int* idx = dir ? iB : iA;
    const float* xyz1 = dir ? xB : xA;
    const float* xyz2 = dir ? xA : xB;
    const float* p1 = dir ? p1B : p1A;
    const float* p2 = dir ? p2B : p2A;
    const float* w3 = dir ? w3B : w3A;
    const float* b3 = dir ? b3B : b3A;
    float* obn = dir ? obnB : obnA;
    float* ocn = dir ? ocnB : ocnA;

    const int tid = threadIdx.x;
    for (int i = tid; i < 4096; i += 256) {
        int jb = i >> 8, c = (i >> 2) & 63, u = i & 3;
        s_w1[i] = w1[c * 64 + jb * 4 + u];
        if (NL == 2) s_w2[i] = w2[c * 64 + jb * 4 + u];
        if (EPI)     s_w3[i] = w3[c * 64 + jb * 4 + u];
    }
    if (tid < 192) s_pwt[tid] = posw[(tid & 63) * 3 + (tid >> 6)];
    if (tid < 64) {
        s_pb[tid] = posb[tid];
        s_b1[tid] = b1[tid];
        if (NL == 2) s_b2[tid] = b2[tid];
        if (EPI)     s_b3[tid] = b3[tid];
    }
    __syncthreads();

    const int warp = tid >> 5, lane = tid & 31;
    ull* shp = s_hp + warp * 512;
    ull* sst = s_st + warp * 256;
    const int wq0 = (blockIdx.x * 8 + warp) * 8;

    const float pw0a = s_pwt[lane],      pw1a = s_pwt[64 + lane],  pw2a = s_pwt[128 + lane];
    const float pw0b = s_pwt[lane + 32], pw1b = s_pwt[96 + lane],  pw2b = s_pwt[160 + lane];
    const float pba = s_pb[lane], pbb = s_pb[lane + 32];
    const ull bd1a = dup2(s_b1[lane]), bd1b = dup2(s_b1[lane + 32]);
    const ull bd2a = (NL == 2) ? dup2(s_b2[lane]) : 0ull;
    const ull bd2b = (NL == 2) ? dup2(s_b2[lane + 32]) : 0ull;

    float pma = 0.f, pmb = 0.f;

    for (int qi = 0; qi < 8; qi++) {
        const int q = wq0 + qi;
        const int b = q >> 13, n = q & (N - 1);
        const int myidx = idx[q * 16 + (lane & 15)];
        const float p1a = p1[q * 64 + lane];
        const float p1b = p1[q * 64 + 32 + lane];
        const float* x1b = xyz1 + b * 3 * N;
        const float qx = x1b[n], qy = x1b[N + n], qz = x1b[2 * N + n];
        const float* x2b = xyz2 + b * 3 * N;
        const float nx = x2b[myidx], ny = x2b[N + myidx], nz = x2b[2 * N + myidx];

        float pva = 0.f, pvb = 0.f;
        #pragma unroll
        for (int k = 0; k < 16; k++) {
            int j = __shfl_sync(FULLMASK, myidx, k);
            float dx = __shfl_sync(FULLMASK, nx, k) - qx;
            float dy = __shfl_sync(FULLMASK, ny, k) - qy;
            float dz = __shfl_sync(FULLMASK, nz, k) - qz;
            const float* p2r = p2 + ((size_t)((b << 13) + j)) * 64;
            float ga = p2r[lane], gb = p2r[lane + 32];
            float pa = pba + dx * pw0a + dy * pw1a + dz * pw2a;
            float pb = pbb + dx * pw0b + dy * pw1b + dz * pw2b;
            float ha = leaky(ga + p1a + pa);
            float hb = leaky(gb + p1b + pb);
            if (k & 1) {
                shp[(k >> 1) * 64 + lane]      = pk2(pva, ha);
                shp[(k >> 1) * 64 + lane + 32] = pk2(pvb, hb);
            } else { pva = ha; pvb = hb; }
        }
        __syncwarp();

        ull ya[8], yb[8];
        #pragma unroll
        for (int k2 = 0; k2 < 8; k2++) { ya[k2] = bd1a; yb[k2] = bd1b; }
        #pragma unroll
        for (int jb = 0; jb < 16; jb++) {
            float4 wa = *(const float4*)(s_w1 + (jb * 64 + lane) * 4);
            float4 wb = *(const float4*)(s_w1 + (jb * 64 + lane + 32) * 4);
            ull wax = dup2(wa.x), way = dup2(wa.y), waz = dup2(wa.z), waw = dup2(wa.w);
            ull wbx = dup2(wb.x), wby = dup2(wb.y), wbz = dup2(wb.z), wbw = dup2(wb.w);
            #pragma unroll
            for (int k2 = 0; k2 < 8; k2++) {
                ulonglong2 h01 = *(const ulonglong2*)(shp + k2 * 64 + jb * 4);
                ulonglong2 h23 = *(const ulonglong2*)(shp + k2 * 64 + jb * 4 + 2);
                ya[k2] = ffma2(h01.x, wax, ya[k2]);
                yb[k2] = ffma2(h01.x, wbx, yb[k2]);
                ya[k2] = ffma2(h01.y, way, ya[k2]);
                yb[k2] = ffma2(h01.y, wby, yb[k2]);
                ya[k2] = ffma2(h23.x, waz, ya[k2]);
                yb[k2] = ffma2(h23.x, wbz, yb[k2]);
                ya[k2] = ffma2(h23.y, waw, ya[k2]);
                yb[k2] = ffma2(h23.y, wbw, yb[k2]);
            }
        }

        if (NL == 2) {
            __syncwarp();
            #pragma unroll
            for (int k2 = 0; k2 < 8; k2++) {
                shp[k2 * 64 + lane]      = lky2(ya[k2]);
                shp[k2 * 64 + lane + 32] = lky2(yb[k2]);
            }
            __syncwarp();
            #pragma unroll
            for (int k2 = 0; k2 < 8; k2++) { ya[k2] = bd2a; yb[k2] = bd2b; }
            #pragma unroll
            for (int jb = 0; jb < 16; jb++) {
                float4 wa = *(const float4*)(s_w2 + (jb * 64 + lane) * 4);
                float4 wb = *(const float4*)(s_w2 + (jb * 64 + lane + 32) * 4);
                ull wax = dup2(wa.x), way = dup2(wa.y), waz = dup2(wa.z), waw = dup2(wa.w);
                ull wbx = dup2(wb.x), wby = dup2(wb.y), wbz = dup2(wb.z), wbw = dup2(wb.w);
                #pragma unroll
                for (int k2 = 0; k2 < 8; k2++) {
                    ulonglong2 h01 = *(const ulonglong2*)(shp + k2 * 64 + jb * 4);
                    ulonglong2 h23 = *(const ulonglong2*)(shp + k2 * 64 + jb * 4 + 2);
                    ya[k2] = ffma2(h01.x, wax, ya[k2]);
                    yb[k2] = ffma2(h01.x, wbx, yb[k2]);
                    ya[k2] = ffma2(h01.y, way, ya[k2]);
                    yb[k2] = ffma2(h01.y, wby, yb[k2]);
                    ya[k2] = ffma2(h23.x, waz, ya[k2]);
                    yb[k2] = ffma2(h23.x, wbz, yb[k2]);
                    ya[k2] = ffma2(h23.y, waw, ya[k2]);
                    yb[k2] = ffma2(h23.y, wbw, yb[k2]);
                }
            }
        }

        float ma = -3.0e38f, mb = -3.0e38f;
        #pragma unroll
        for (int k2 = 0; k2 < 8; k2++) {
            float u, v;
            unpk2(u, v, ya[k2]); ma = fmaxf(ma, fmaxf(u, v));
            unpk2(u, v, yb[k2]); mb = fmaxf(mb, fmaxf(u, v));
        }
        ma = leaky(ma); mb = leaky(mb);

        if (EPI) {
            if (qi & 1) {
                sst[(qi >> 1) * 64 + lane]      = pk2(pma, ma);
                sst[(qi >> 1) * 64 + 32 + lane] = pk2(pmb, mb);
            } else { pma = ma; pmb = mb; }
        } else {
            // transposed direct write (cross3)
            ocn[((b * 64) + lane) * N + n] = ma;
            ocn[((b * 64) + lane + 32) * N + n] = mb;
        }
        __syncwarp();
    }

    if (EPI) {
        __syncwarp();
        ull za[4], zb[4];
        const ull bd3a = dup2(s_b3[lane]), bd3b = dup2(s_b3[lane + 32]);
        #pragma unroll
        for (int q2 = 0; q2 < 4; q2++) { za[q2] = bd3a; zb[q2] = bd3b; }
        #pragma unroll
        for (int jb = 0; jb < 16; jb++) {
            float4 wa = *(const float4*)(s_w3 + (jb * 64 + lane) * 4);
            float4 wb = *(const float4*)(s_w3 + (jb * 64 + lane + 32) * 4);
            ull wax = dup2(wa.x), way = dup2(wa.y), waz = dup2(wa.z), waw = dup2(wa.w);
            ull wbx = dup2(wb.x), wby = dup2(wb.y), wbz = dup2(wb.z), wbw = dup2(wb.w);
            #pragma unroll
            for (int q2 = 0; q2 < 4; q2++) {
                ulonglong2 h01 = *(const ulonglong2*)(sst + q2 * 64 + jb * 4);
                ulonglong2 h23 = *(const ulonglong2*)(sst + q2 * 64 + jb * 4 + 2);
                za[q2] = ffma2(h01.x, wax, za[q2]);
                zb[q2] = ffma2(h01.x, wbx, zb[q2]);
                za[q2] = ffma2(h01.y, way, za[q2]);
                zb[q2] = ffma2(h01.y, wby, zb[q2]);
                za[q2] = ffma2(h23.x, waz, za[q2]);
                zb[q2] = ffma2(h23.x, wbz, zb[q2]);
                za[q2] = ffma2(h23.y, waw, za[q2]);
                zb[q2] = ffma2(h23.y, wbw, zb[q2]);
            }
        }
        #pragma unroll
        for (int q2 = 0; q2 < 4; q2++) {
            const int q = wq0 + 2 * q2;
            const int b = q >> 13, n = q & (N - 1);
            float lo, hi;
            unpk2(lo, hi, za[q2]);
            obn[q * 64 + lane] = lo;
            obn[(q + 1) * 64 + lane] = hi;
            *(float2*)&ocn[((b * 64) + lane) * N + n] = make_float2(lo, hi);
            unpk2(lo, hi, zb[q2]);
            obn[q * 64 + 32 + lane] = lo;
            obn[(q + 1) * 64 + 32 + lane] = hi;
            *(float2*)&ocn[((b * 64) + lane + 32) * N + n] = make_float2(lo, hi);
        }
    }
}

// ---------------- launch ----------------
extern "C" void kernel_launch(void* const* d_in, const int* in_sizes, int n_in,
                              void* d_out, int out_size)
{
    const float* pc1     = (const float*)d_in[0];
    const float* pc2     = (const float*)d_in[1];
    const float* feat1   = (const float*)d_in[2];
    const float* feat2   = (const float*)d_in[3];
    const float* t11_w   = (const float*)d_in[4];
    const float* t11_b   = (const float*)d_in[5];
    const float* t22_w   = (const float*)d_in[6];
    const float* t22_b   = (const float*)d_in[7];
    const float* pos1_w  = (const float*)d_in[8];
    const float* pos1_b  = (const float*)d_in[9];
    const float* mlp1_w1 = (const float*)d_in[10];
    const float* mlp1_b1 = (const float*)d_in[11];
    const float* mlp1_w2 = (const float*)d_in[12];
    const float* mlp1_b2 = (const float*)d_in[13];
    const float* t1_w    = (const float*)d_in[14];
    const float* t1_b    = (const float*)d_in[15];
    const float* t2_w    = (const float*)d_in[16];
    const float* t2_b    = (const float*)d_in[17];
    const float* pos2_w  = (const float*)d_in[18];
    const float* pos2_b  = (const float*)d_in[19];
    const float* mlp2_w1 = (const float*)d_in[20];
    const float* mlp2_b1 = (const float*)d_in[21];
    float* out = (float*)d_out;

    float *q1, *q2, *r1, *r2, *f1, *f2;
    int *i12, *i21;
    cudaGetSymbolAddress((void**)&q1, g_q1);
    cudaGetSymbolAddress((void**)&q2, g_q2);
    cudaGetSymbolAddress((void**)&r1, g_r1);
    cudaGetSymbolAddress((void**)&r2, g_r2);
    cudaGetSymbolAddress((void**)&f1, g_f1);
    cudaGetSymbolAddress((void**)&f2, g_f2);
    cudaGetSymbolAddress((void**)&i12, g_i12);
    cudaGetSymbolAddress((void**)&i21, g_i21);

    // fused KNN (z=0,1; grid.x<256 active) + transforms (z=2; grid.x<512 active)
    const size_t smem_kt = (size_t)TILE / 2 * 32;   // 64KB
    cudaFuncSetAttribute(knn_transform_kernel, cudaFuncAttributeMaxDynamicSharedMemorySize, (int)smem_kt);
    knn_transform_kernel<<<dim3(N / 16, BB, 3), 512, smem_kt>>>(
        pc1, pc2, i12, i21,
        feat1, feat2, t11_w, t11_b, t22_w, t22_b,
        q1, q2, r1, r2);

    const size_t smem = (size_t)SMEM_FLOATS * sizeof(float);
    cudaFuncSetAttribute(cross_kernel<2,1>, cudaFuncAttributeMaxDynamicSharedMemorySize, (int)smem);
    cudaFuncSetAttribute(cross_kernel<1,0>, cudaFuncAttributeMaxDynamicSharedMemorySize, (int)smem);

    // cross 1 & 2 fused (grid.y = direction) with final-linear epilogue
    cross_kernel<2,1><<<dim3(BB * N / 64, 2), 256, smem>>>(
        i12, i21, pc1, pc2,
        q1, q2, r1, r2,
        pos1_w, pos1_b, mlp1_w1, mlp1_b1, mlp1_w2, mlp1_b2,
        t1_w, t1_b, t2_w, t2_b,
        f1, f2, out, out + (size_t)BB * 64 * N);

    // cross 3 (1 mlp layer), transposed direct write to output region 2
    cross_kernel<1,0><<<dim3(BB * N / 64, 1), 256, smem>>>(
        i12, i12, pc1, pc2,
        f1, f2, f1, f2,
        pos2_w, pos2_b, mlp2_w1, mlp2_b1, mlp2_w1, mlp2_b1,
        mlp2_w1, mlp2_b1, mlp2_w1, mlp2_b1,
        out + (size_t)2 * BB * 64 * N, out + (size_t)2 * BB * 64 * N,
        out + (size_t)2 * BB * 64 * N, out + (size_t)2 * BB * 64 * N);
}

// round 7
// speedup vs baseline: 1.0877x; 1.0477x over previous
#include <cuda_runtime.h>

#define N 8192
#define BB 2
#define CH 64
#define KNB 16
#define FULLMASK 0xffffffffu
typedef unsigned long long ull;

// ---------------- scratch (static device globals; no allocation) ----------------
__device__ float g_q1[BB*N*CH];
__device__ float g_q2[BB*N*CH];
__device__ float g_r1[BB*N*CH];
__device__ float g_r2[BB*N*CH];
__device__ float g_f1[BB*N*CH];
__device__ float g_f2[BB*N*CH];
__device__ int   g_i12[BB*N*KNB];
__device__ int   g_i21[BB*N*KNB];

__device__ __forceinline__ float leaky(float x) { return fmaxf(x, 0.1f * x); }

// ---------------- packed f32x2 helpers ----------------
__device__ __forceinline__ ull ffma2(ull a, ull b, ull c) {
    ull d; asm("fma.rn.f32x2 %0, %1, %2, %3;" : "=l"(d) : "l"(a), "l"(b), "l"(c)); return d;
}
__device__ __forceinline__ ull pk2(float x, float y) {
    ull r; asm("mov.b64 %0, {%1, %2};" : "=l"(r) : "f"(x), "f"(y)); return r;
}
__device__ __forceinline__ ull dup2(float x) {
    ull r; asm("mov.b64 %0, {%1, %1};" : "=l"(r) : "f"(x)); return r;
}
__device__ __forceinline__ void unpk2(float& lo, float& hi, ull v) {
    asm("mov.b64 {%0, %1}, %2;" : "=f"(lo), "=f"(hi) : "l"(v));
}
__device__ __forceinline__ ull lky2(ull v) {
    float a, b; unpk2(a, b, v);
    return pk2(fmaxf(a, 0.1f * a), fmaxf(b, 0.1f * b));
}

// ================= fused KNN (z=0,1; 2 queries/warp) + 4-way transform (z=2) =================
#define TILE 2048   // points per smem tile (1024 pairs * 32B = 32KB) -> 4 blocks/SM

__global__ __launch_bounds__(512, 4) void knn_transform_kernel(
    const float* __restrict__ pc1, const float* __restrict__ pc2,
    int* __restrict__ i12, int* __restrict__ i21,
    const float* __restrict__ f1g, const float* __restrict__ f2g,
    const float* __restrict__ w11, const float* __restrict__ b11,
    const float* __restrict__ w22, const float* __restrict__ b22,
    float* __restrict__ q1o, float* __restrict__ q2o,
    float* __restrict__ r1o, float* __restrict__ r2o)
{
    extern __shared__ char smraw[];
    const int tid = threadIdx.x;

    if (blockIdx.z == 2) {
        // ---- 4-way feature transform: 16 points per block (uses 48KB smem) ----
        ull* s_wp  = (ull*)smraw;       // 4096: [c][m] = (w11[m][c], w22[m][c])
        ull* s_f12 = s_wp + 4096;       // 1024: [c][np] = (f1, f2)
        ull* s_f21 = s_f12 + 1024;      // 1024: [c][np] = (f2, f1)
        const int b = blockIdx.y, n0 = blockIdx.x * 16;
        for (int i = tid; i < 4096; i += 512) {
            int m = i >> 6, c = i & 63;
            s_wp[c * 64 + m] = pk2(w11[i], w22[i]);
        }
        for (int i = tid; i < 1024; i += 512) {
            int c = i >> 4, np = i & 15;
            float a = f1g[(b * 64 + c) * N + n0 + np];
            float d = f2g[(b * 64 + c) * N + n0 + np];
            s_f12[i] = pk2(a, d);
            s_f21[i] = pk2(d, a);
        }
        __syncthreads();
        const int m = tid & 63, grp = tid >> 6;  // grp 0..7, 2 points each
        ull bq = pk2(b11[m], b22[m]);
        ull a0 = bq, a1 = bq, r0 = bq, r1v = bq;
        const int np = grp * 2;
        #pragma unroll 8
        for (int c = 0; c < 64; c++) {
            ull wv = s_wp[c * 64 + m];
            a0  = ffma2(s_f12[c * 16 + np],     wv, a0);
            a1  = ffma2(s_f12[c * 16 + np + 1], wv, a1);
            r0  = ffma2(s_f21[c * 16 + np],     wv, r0);
            r1v = ffma2(s_f21[c * 16 + np + 1], wv, r1v);
        }
        float v1, v2;
        int q = (b * N + n0 + np) * 64 + m;
        unpk2(v1, v2, a0);  q1o[q] = v1;      q2o[q] = v2;
        unpk2(v1, v2, a1);  q1o[q + 64] = v1; q2o[q + 64] = v2;
        unpk2(v1, v2, r0);  r1o[q] = v1;      r2o[q] = v2;
        unpk2(v1, v2, r1v); r1o[q + 64] = v1; r2o[q + 64] = v2;
        return;
    }

    // ---- KNN: 2 queries per warp, top-16 list per 16-lane half ----
    if (blockIdx.x >= N / 32) return;
    ulonglong2* s_t0 = (ulonglong2*)smraw;     // 1024: (x-pair, y-pair)
    ulonglong2* s_t1 = s_t0 + (TILE / 2);      // 1024: (z-pair, |p|^2-pair)
    const int dir = blockIdx.z;
    const float* q  = dir ? pc2 : pc1;
    const float* db = dir ? pc1 : pc2;
    int* oi = dir ? i21 : i12;
    const int b = blockIdx.y;
    const int warp = tid >> 5, lane = tid & 31;
    const int nA = blockIdx.x * 32 + warp * 2;
    const int nB = nA + 1;
    const float* qb = q + b * 3 * N;
    const ull m2qAx = dup2(-2.0f * qb[nA]);
    const ull m2qAy = dup2(-2.0f * qb[N + nA]);
    const ull m2qAz = dup2(-2.0f * qb[2 * N + nA]);
    const ull m2qBx = dup2(-2.0f * qb[nB]);
    const ull m2qBy = dup2(-2.0f * qb[N + nB]);
    const ull m2qBz = dup2(-2.0f * qb[2 * N + nB]);
    const float* dbb = db + b * 3 * N;

    float bd = 3.0e38f;   // sorted ascending within each 16-lane half
    int bi = 0;
    float tauA = 3.0e38f, tauB = 3.0e38f;
    const bool halfA = (lane < 16);

    for (int t = 0; t < N; t += TILE) {
        __syncthreads();
        const float2* gx = (const float2*)(dbb + t);
        const float2* gy = (const float2*)(dbb + N + t);
        const float2* gz = (const float2*)(dbb + 2 * N + t);
        for (int i = tid; i < TILE / 2; i += 512) {
            float2 x = gx[i], y = gy[i], z = gz[i];
            float w0 = x.x * x.x + y.x * y.x + z.x * z.x;
            float w1 = x.y * x.y + y.y * y.y + z.y * z.y;
            ulonglong2 A, B;
            A.x = *(const ull*)&x; A.y = *(const ull*)&y;
            B.x = *(const ull*)&z; B.y = pk2(w0, w1);
            s_t0[i] = A; s_t1[i] = B;
        }
        __syncthreads();
        for (int p = 0; p < TILE / 2; p += 32) {
            ulonglong2 t0 = s_t0[p + lane];
            ulonglong2 t1 = s_t1[p + lane];
            ull dA = ffma2(t0.x, m2qAx, t1.y);
            dA = ffma2(t0.y, m2qAy, dA);
            dA = ffma2(t1.x, m2qAz, dA);
            ull dB = ffma2(t0.x, m2qBx, t1.y);
            dB = ffma2(t0.y, m2qBy, dB);
            dB = ffma2(t1.x, m2qBz, dB);
            float dA0, dA1, dB0, dB1;
            unpk2(dA0, dA1, dA);
            unpk2(dB0, dB1, dB);
            bool hit = (fminf(dA0, dA1) < tauA) | (fminf(dB0, dB1) < tauB);
            if (__ballot_sync(FULLMASK, hit)) {
                const int base = t + 2 * p;
                unsigned mA0 = __ballot_sync(FULLMASK, dA0 < tauA);
                unsigned mA1 = __ballot_sync(FULLMASK, dA1 < tauA);
                unsigned mB0 = __ballot_sync(FULLMASK, dB0 < tauB);
                unsigned mB1 = __ballot_sync(FULLMASK, dB1 < tauB);
                unsigned mm0 = halfA ? mA0 : mB0;
                unsigned mm1 = halfA ? mA1 : mB1;
                // element-0 candidates
                while (__ballot_sync(FULLMASK, mm0 != 0)) {
                    int src = __ffs(mm0) - 1;
                    float vA = __shfl_sync(FULLMASK, dA0, src & 31);
                    float vB = __shfl_sync(FULLMASK, dB0, src & 31);
                    float dd = halfA ? vA : vB;
                    float up  = __shfl_up_sync(FULLMASK, bd, 1, 16);
                    int   upi = __shfl_up_sync(FULLMASK, bi, 1, 16);
                    if ((lane & 15) == 0) up = -3.0e38f;
                    if (mm0 && bd > dd) {
                        bool tk = up > dd;
                        bd = tk ? up : dd;
                        bi = tk ? upi : base + 2 * src;
                    }
                    mm0 &= mm0 - 1;
                }
                // element-1 candidates
                while (__ballot_sync(FULLMASK, mm1 != 0)) {
                    int src = __ffs(mm1) - 1;
                    float vA = __shfl_sync(FULLMASK, dA1, src & 31);
                    float vB = __shfl_sync(FULLMASK, dB1, src & 31);
                    float dd = halfA ? vA : vB;
                    float up  = __shfl_up_sync(FULLMASK, bd, 1, 16);
                    int   upi = __shfl_up_sync(FULLMASK, bi, 1, 16);
                    if ((lane & 15) == 0) up = -3.0e38f;
                    if (mm1 && bd > dd) {
                        bool tk = up > dd;
                        bd = tk ? up : dd;
                        bi = tk ? upi : base + 2 * src + 1;
                    }
                    mm1 &= mm1 - 1;
                }
                tauA = __shfl_sync(FULLMASK, bd, 15);
                tauB = __shfl_sync(FULLMASK, bd, 31);
            }
        }
    }
    const int nOut = halfA ? nA : nB;
    oi[((b * N) + nOut) * 16 + (lane & 15)] = bi;
}

// ================= fused cross (+ optional final-linear epilogue) =================
// 4 queries per warp; 8 warps per block.
// smem float offsets
#define OW1 0
#define OW2 4096
#define OW3 8192
#define OPWT 12288
#define OPB  12480
#define OB1  12544
#define OB2  12608
#define OB3  12672
#define OHP  12736                 // ull region: 8 warps * 512 = 4096 ull
#define OST  (12736 + 4096*2)      // float offset of stash: 8 warps * 256 ull
#define SMEM_FLOATS (12736 + 4096*2 + 2048*2)

template <int NL, int EPI>
__global__ __launch_bounds__(256) void cross_kernel(
    const int* __restrict__ iA, const int* __restrict__ iB,
    const float* __restrict__ xA, const float* __restrict__ xB,
    const float* __restrict__ p1A, const float* __restrict__ p2A,
    const float* __restrict__ p1B, const float* __restrict__ p2B,
    const float* __restrict__ posw, const float* __restrict__ posb,
    const float* __restrict__ w1, const float* __restrict__ b1,
    const float* __restrict__ w2, const float* __restrict__ b2,
    const float* __restrict__ w3A, const float* __restrict__ b3A,
    const float* __restrict__ w3B, const float* __restrict__ b3B,
    float* __restrict__ obnA, float* __restrict__ obnB,
    float* __restrict__ ocnA, float* __restrict__ ocnB)
{
    extern __shared__ float sm[];
    float* s_w1  = sm + OW1;
    float* s_w2  = sm + OW2;
    float* s_w3  = sm + OW3;
    float* s_pwt = sm + OPWT;
    float* s_pb  = sm + OPB;
    float* s_b1  = sm + OB1;
    float* s_b2  = sm + OB2;
    float* s_b3  = sm + OB3;
    ull*   s_hp  = (ull*)(sm + OHP);
    ull*   s_st  = (ull*)(sm + OST);

    const int dir = blockIdx.y;
    const int* idx = dir ? iB : iA;
    const float* xyz1 = dir ? xB : xA;
    const float* xyz2 = dir ? xA : xB;
    const float* p1 = dir ? p1B : p1A;
    const float* p2 = dir ? p2B : p2A;
    const float* w3 = dir ? w3B : w3A;
    const float* b3 = dir ? b3B : b3A;
    float* obn = dir ? obnB : obnA;
    float* ocn = dir ? ocnB : ocnA;

    const int tid = threadIdx.x;
    for (int i = tid; i < 4096; i += 256) {
        int jb = i >> 8, c = (i >> 2) & 63, u = i & 3;
        s_w1[i] = w1[c * 64 + jb * 4 + u];
        if (NL == 2) s_w2[i] = w2[c * 64 + jb * 4 + u];
        if (EPI)     s_w3[i] = w3[c * 64 + jb * 4 + u];
    }
    if (tid < 192) s_pwt[tid] = posw[(tid & 63) * 3 + (tid >> 6)];
    if (tid < 64) {
        s_pb[tid] = posb[tid];
        s_b1[tid] = b1[tid];
        if (NL == 2) s_b2[tid] = b2[tid];
        if (EPI)     s_b3[tid] = b3[tid];
    }
    __syncthreads();

    const int warp = tid >> 5, lane = tid & 31;
    ull* shp = s_hp + warp * 512;
    ull* sst = s_st + warp * 256;
    const int wq0 = (blockIdx.x * 8 + warp) * 4;

    const float pw0a = s_pwt[lane],      pw1a = s_pwt[64 + lane],  pw2a = s_pwt[128 + lane];
    const float pw0b = s_pwt[lane + 32], pw1b = s_pwt[96 + lane],  pw2b = s_pwt[160 + lane];
    const float pba = s_pb[lane], pbb = s_pb[lane + 32];
    const ull bd1a = dup2(s_b1[lane]), bd1b = dup2(s_b1[lane + 32]);
    const ull bd2a = (NL == 2) ? dup2(s_b2[lane]) : 0ull;
    const ull bd2b = (NL == 2) ? dup2(s_b2[lane + 32]) : 0ull;

    float pma = 0.f, pmb = 0.f;

    for (int qi = 0; qi < 4; qi++) {
        const int q = wq0 + qi;
        const int b = q >> 13, n = q & (N - 1);
        const int myidx = idx[q * 16 + (lane & 15)];
        const float p1a = p1[q * 64 + lane];
        const float p1b = p1[q * 64 + 32 + lane];
        const float* x1b = xyz1 + b * 3 * N;
        const float qx = x1b[n], qy = x1b[N + n], qz = x1b[2 * N + n];
        const float* x2b = xyz2 + b * 3 * N;
        const float nx = x2b[myidx], ny = x2b[N + myidx], nz = x2b[2 * N + myidx];

        float pva = 0.f, pvb = 0.f;
        #pragma unroll
        for (int k = 0; k < 16; k++) {
            int j = __shfl_sync(FULLMASK, myidx, k);
            float dx = __shfl_sync(FULLMASK, nx, k) - qx;
            float dy = __shfl_sync(FULLMASK, ny, k) - qy;
            float dz = __shfl_sync(FULLMASK, nz, k) - qz;
            const float* p2r = p2 + ((size_t)((b << 13) + j)) * 64;
            float ga = p2r[lane], gb = p2r[lane + 32];
            float pa = pba + dx * pw0a + dy * pw1a + dz * pw2a;
            float pb = pbb + dx * pw0b + dy * pw1b + dz * pw2b;
            float ha = leaky(ga + p1a + pa);
            float hb = leaky(gb + p1b + pb);
            if (k & 1) {
                shp[(k >> 1) * 64 + lane]      = pk2(pva, ha);
                shp[(k >> 1) * 64 + lane + 32] = pk2(pvb, hb);
            } else { pva = ha; pvb = hb; }
        }
        __syncwarp();

        ull ya[8], yb[8];
        #pragma unroll
        for (int k2 = 0; k2 < 8; k2++) { ya[k2] = bd1a; yb[k2] = bd1b; }
        #pragma unroll
        for (int jb = 0; jb < 16; jb++) {
            float4 wa = *(const float4*)(s_w1 + (jb * 64 + lane) * 4);
            float4 wb = *(const float4*)(s_w1 + (jb * 64 + lane + 32) * 4);
            ull wax = dup2(wa.x), way = dup2(wa.y), waz = dup2(wa.z), waw = dup2(wa.w);
            ull wbx = dup2(wb.x), wby = dup2(wb.y), wbz = dup2(wb.z), wbw = dup2(wb.w);
            #pragma unroll
            for (int k2 = 0; k2 < 8; k2++) {
                ulonglong2 h01 = *(const ulonglong2*)(shp + k2 * 64 + jb * 4);
                ulonglong2 h23 = *(const ulonglong2*)(shp + k2 * 64 + jb * 4 + 2);
                ya[k2] = ffma2(h01.x, wax, ya[k2]);
                yb[k2] = ffma2(h01.x, wbx, yb[k2]);
                ya[k2] = ffma2(h01.y, way, ya[k2]);
                yb[k2] = ffma2(h01.y, wby, yb[k2]);
                ya[k2] = ffma2(h23.x, waz, ya[k2]);
                yb[k2] = ffma2(h23.x, wbz, yb[k2]);
                ya[k2] = ffma2(h23.y, waw, ya[k2]);
                yb[k2] = ffma2(h23.y, wbw, yb[k2]);
            }
        }

        if (NL == 2) {
            __syncwarp();
            #pragma unroll
            for (int k2 = 0; k2 < 8; k2++) {
                shp[k2 * 64 + lane]      = lky2(ya[k2]);
                shp[k2 * 64 + lane + 32] = lky2(yb[k2]);
            }
            __syncwarp();
            #pragma unroll
            for (int k2 = 0; k2 < 8; k2++) { ya[k2] = bd2a; yb[k2] = bd2b; }
            #pragma unroll
            for (int jb = 0; jb < 16; jb++) {
                float4 wa = *(const float4*)(s_w2 + (jb * 64 + lane) * 4);
                float4 wb = *(const float4*)(s_w2 + (jb * 64 + lane + 32) * 4);
                ull wax = dup2(wa.x), way = dup2(wa.y), waz = dup2(wa.z), waw = dup2(wa.w);
                ull wbx = dup2(wb.x), wby = dup2(wb.y), wbz = dup2(wb.z), wbw = dup2(wb.w);
                #pragma unroll
                for (int k2 = 0; k2 < 8; k2++) {
                    ulonglong2 h01 = *(const ulonglong2*)(shp + k2 * 64 + jb * 4);
                    ulonglong2 h23 = *(const ulonglong2*)(shp + k2 * 64 + jb * 4 + 2);
                    ya[k2] = ffma2(h01.x, wax, ya[k2]);
                    yb[k2] = ffma2(h01.x, wbx, yb[k2]);
                    ya[k2] = ffma2(h01.y, way, ya[k2]);
                    yb[k2] = ffma2(h01.y, wby, yb[k2]);
                    ya[k2] = ffma2(h23.x, waz, ya[k2]);
                    yb[k2] = ffma2(h23.x, wbz, yb[k2]);
                    ya[k2] = ffma2(h23.y, waw, ya[k2]);
                    yb[k2] = ffma2(h23.y, wbw, yb[k2]);
                }
            }
        }

        float ma = -3.0e38f, mb = -3.0e38f;
        #pragma unroll
        for (int k2 = 0; k2 < 8; k2++) {
            float u, v;
            unpk2(u, v, ya[k2]); ma = fmaxf(ma, fmaxf(u, v));
            unpk2(u, v, yb[k2]); mb = fmaxf(mb, fmaxf(u, v));
        }
        ma = leaky(ma); mb = leaky(mb);

        if (EPI) {
            if (qi & 1) {
                sst[(qi >> 1) * 64 + lane]      = pk2(pma, ma);
                sst[(qi >> 1) * 64 + 32 + lane] = pk2(pmb, mb);
            } else { pma = ma; pmb = mb; }
        } else {
            // transposed direct write (cross3)
            ocn[((b * 64) + lane) * N + n] = ma;
            ocn[((b * 64) + lane + 32) * N + n] = mb;
        }
        __syncwarp();
    }

    if (EPI) {
        __syncwarp();
        ull za[2], zb[2];
        const ull bd3a = dup2(s_b3[lane]), bd3b = dup2(s_b3[lane + 32]);
        #pragma unroll
        for (int q2 = 0; q2 < 2; q2++) { za[q2] = bd3a; zb[q2] = bd3b; }
        #pragma unroll
        for (int jb = 0; jb < 16; jb++) {
            float4 wa = *(const float4*)(s_w3 + (jb * 64 + lane) * 4);
            float4 wb = *(const float4*)(s_w3 + (jb * 64 + lane + 32) * 4);
            ull wax = dup2(wa.x), way = dup2(wa.y), waz = dup2(wa.z), waw = dup2(wa.w);
            ull wbx = dup2(wb.x), wby = dup2(wb.y), wbz = dup2(wb.z), wbw = dup2(wb.w);
            #pragma unroll
            for (int q2 = 0; q2 < 2; q2++) {
                ulonglong2 h01 = *(const ulonglong2*)(sst + q2 * 64 + jb * 4);
                ulonglong2 h23 = *(const ulonglong2*)(sst + q2 * 64 + jb * 4 + 2);
                za[q2] = ffma2(h01.x, wax, za[q2]);
                zb[q2] = ffma2(h01.x, wbx, zb[q2]);
                za[q2] = ffma2(h01.y, way, za[q2]);
                zb[q2] = ffma2(h01.y, wby, zb[q2]);
                za[q2] = ffma2(h23.x, waz, za[q2]);
                zb[q2] = ffma2(h23.x, wbz, zb[q2]);
                za[q2] = ffma2(h23.y, waw, za[q2]);
                zb[q2] = ffma2(h23.y, wbw, zb[q2]);
            }
        }
        #pragma unroll
        for (int q2 = 0; q2 < 2; q2++) {
            const int q = wq0 + 2 * q2;
            const int b = q >> 13, n = q & (N - 1);
            float lo, hi;
            unpk2(lo, hi, za[q2]);
            obn[q * 64 + lane] = lo;
            obn[(q + 1) * 64 + lane] = hi;
            *(float2*)&ocn[((b * 64) + lane) * N + n] = make_float2(lo, hi);
            unpk2(lo, hi, zb[q2]);
            obn[q * 64 + 32 + lane] = lo;
            obn[(q + 1) * 64 + 32 + lane] = hi;
            *(float2*)&ocn[((b * 64) + lane + 32) * N + n] = make_float2(lo, hi);
        }
    }
}

// ---------------- launch ----------------
extern "C" void kernel_launch(void* const* d_in, const int* in_sizes, int n_in,
                              void* d_out, int out_size)
{
    const float* pc1     = (const float*)d_in[0];
    const float* pc2     = (const float*)d_in[1];
    const float* feat1   = (const float*)d_in[2];
    const float* feat2   = (const float*)d_in[3];
    const float* t11_w   = (const float*)d_in[4];
    const float* t11_b   = (const float*)d_in[5];
    const float* t22_w   = (const float*)d_in[6];
    const float* t22_b   = (const float*)d_in[7];
    const float* pos1_w  = (const float*)d_in[8];
    const float* pos1_b  = (const float*)d_in[9];
    const float* mlp1_w1 = (const float*)d_in[10];
    const float* mlp1_b1 = (const float*)d_in[11];
    const float* mlp1_w2 = (const float*)d_in[12];
    const float* mlp1_b2 = (const float*)d_in[13];
    const float* t1_w    = (const float*)d_in[14];
    const float* t1_b    = (const float*)d_in[15];
    const float* t2_w    = (const float*)d_in[16];
    const float* t2_b    = (const float*)d_in[17];
    const float* pos2_w  = (const float*)d_in[18];
    const float* pos2_b  = (const float*)d_in[19];
    const float* mlp2_w1 = (const float*)d_in[20];
    const float* mlp2_b1 = (const float*)d_in[21];
    float* out = (float*)d_out;

    float *q1, *q2, *r1, *r2, *f1, *f2;
    int *i12, *i21;
    cudaGetSymbolAddress((void**)&q1, g_q1);
    cudaGetSymbolAddress((void**)&q2, g_q2);
    cudaGetSymbolAddress((void**)&r1, g_r1);
    cudaGetSymbolAddress((void**)&r2, g_r2);
    cudaGetSymbolAddress((void**)&f1, g_f1);
    cudaGetSymbolAddress((void**)&f2, g_f2);
    cudaGetSymbolAddress((void**)&i12, g_i12);
    cudaGetSymbolAddress((void**)&i21, g_i21);

    // fused KNN (z=0,1; grid.x<256 active, 32KB used) + transforms (z=2; 48KB used)
    const size_t smem_kt = 49152;   // 48KB -> 4 blocks/SM, 100% occupancy
    cudaFuncSetAttribute(knn_transform_kernel, cudaFuncAttributeMaxDynamicSharedMemorySize, (int)smem_kt);
    knn_transform_kernel<<<dim3(N / 16, BB, 3), 512, smem_kt>>>(
        pc1, pc2, i12, i21,
        feat1, feat2, t11_w, t11_b, t22_w, t22_b,
        q1, q2, r1, r2);

    const size_t smem = (size_t)SMEM_FLOATS * sizeof(float);
    cudaFuncSetAttribute(cross_kernel<2,1>, cudaFuncAttributeMaxDynamicSharedMemorySize, (int)smem);
    cudaFuncSetAttribute(cross_kernel<1,0>, cudaFuncAttributeMaxDynamicSharedMemorySize, (int)smem);

    // cross 1 & 2 fused (grid.y = direction) with final-linear epilogue; 4 queries/warp
    cross_kernel<2,1><<<dim3(BB * N / 32, 2), 256, smem>>>(
        i12, i21, pc1, pc2,
        q1, q2, r1, r2,
        pos1_w, pos1_b, mlp1_w1, mlp1_b1, mlp1_w2, mlp1_b2,
        t1_w, t1_b, t2_w, t2_b,
        f1, f2, out, out + (size_t)BB * 64 * N);

    // cross 3 (1 mlp layer), transposed direct write to output region 2
    cross_kernel<1,0><<<dim3(BB * N / 32, 1), 256, smem>>>(
        i12, i12, pc1, pc2,
        f1, f2, f1, f2,
        pos2_w, pos2_b, mlp2_w1, mlp2_b1, mlp2_w1, mlp2_b1,
        mlp2_w1, mlp2_b1, mlp2_w1, mlp2_b1,
        out + (size_t)2 * BB * 64 * N, out + (size_t)2 * BB * 64 * N,
        out + (size_t)2 * BB * 64 * N, out + (size_t)2 * BB * 64 * N);
}

// round 8
// speedup vs baseline: 1.4441x; 1.3277x over previous
#include <cuda_runtime.h>

#define N 8192
#define BB 2
#define CH 64
#define KNB 16
#define FULLMASK 0xffffffffu
typedef unsigned long long ull;
typedef unsigned int uint;

// ---------------- scratch (static device globals; no allocation) ----------------
__device__ float g_q1[BB*N*CH];
__device__ float g_q2[BB*N*CH];
__device__ float g_r1[BB*N*CH];
__device__ float g_r2[BB*N*CH];
__device__ float g_f1[BB*N*CH];
__device__ float g_f2[BB*N*CH];
__device__ int   g_i12[BB*N*KNB];
__device__ int   g_i21[BB*N*KNB];

__device__ __forceinline__ float leaky(float x) { return fmaxf(x, 0.1f * x); }

// ---------------- packed f32x2 helpers (knn/transform) ----------------
__device__ __forceinline__ ull ffma2(ull a, ull b, ull c) {
    ull d; asm("fma.rn.f32x2 %0, %1, %2, %3;" : "=l"(d) : "l"(a), "l"(b), "l"(c)); return d;
}
__device__ __forceinline__ ull pk2(float x, float y) {
    ull r; asm("mov.b64 %0, {%1, %2};" : "=l"(r) : "f"(x), "f"(y)); return r;
}
__device__ __forceinline__ ull dup2(float x) {
    ull r; asm("mov.b64 %0, {%1, %1};" : "=l"(r) : "f"(x)); return r;
}
__device__ __forceinline__ void unpk2(float& lo, float& hi, ull v) {
    asm("mov.b64 {%0, %1}, %2;" : "=f"(lo), "=f"(hi) : "l"(v));
}

// ---------------- tf32 helpers (cross) ----------------
__device__ __forceinline__ uint tf32r(float x) {
    uint u; asm("cvt.rna.tf32.f32 %0, %1;" : "=r"(u) : "f"(x)); return u;
}
__device__ __forceinline__ void mma_tf32(float* d, uint a0, uint a1, uint a2, uint a3,
                                         uint b0, uint b1) {
    asm volatile(
        "mma.sync.aligned.m16n8k8.row.col.f32.tf32.tf32.f32 "
        "{%0,%1,%2,%3}, {%4,%5,%6,%7}, {%8,%9}, {%0,%1,%2,%3};"
        : "+f"(d[0]), "+f"(d[1]), "+f"(d[2]), "+f"(d[3])
        : "r"(a0), "r"(a1), "r"(a2), "r"(a3), "r"(b0), "r"(b1));
}

// ================= fused KNN (z=0,1; 2 queries/warp) + 4-way transform (z=2) =================
#define TILE 2048   // 32KB tile -> 4 blocks/SM

__global__ __launch_bounds__(512, 4) void knn_transform_kernel(
    const float* __restrict__ pc1, const float* __restrict__ pc2,
    int* __restrict__ i12, int* __restrict__ i21,
    const float* __restrict__ f1g, const float* __restrict__ f2g,
    const float* __restrict__ w11, const float* __restrict__ b11,
    const float* __restrict__ w22, const float* __restrict__ b22,
    float* __restrict__ q1o, float* __restrict__ q2o,
    float* __restrict__ r1o, float* __restrict__ r2o)
{
    extern __shared__ char smraw[];
    const int tid = threadIdx.x;

    if (blockIdx.z == 2) {
        ull* s_wp  = (ull*)smraw;
        ull* s_f12 = s_wp + 4096;
        ull* s_f21 = s_f12 + 1024;
        const int b = blockIdx.y, n0 = blockIdx.x * 16;
        for (int i = tid; i < 4096; i += 512) {
            int m = i >> 6, c = i & 63;
            s_wp[c * 64 + m] = pk2(w11[i], w22[i]);
        }
        for (int i = tid; i < 1024; i += 512) {
            int c = i >> 4, np = i & 15;
            float a = f1g[(b * 64 + c) * N + n0 + np];
            float d = f2g[(b * 64 + c) * N + n0 + np];
            s_f12[i] = pk2(a, d);
            s_f21[i] = pk2(d, a);
        }
        __syncthreads();
        const int m = tid & 63, grp = tid >> 6;
        ull bq = pk2(b11[m], b22[m]);
        ull a0 = bq, a1 = bq, r0 = bq, r1v = bq;
        const int np = grp * 2;
        #pragma unroll 8
        for (int c = 0; c < 64; c++) {
            ull wv = s_wp[c * 64 + m];
            a0  = ffma2(s_f12[c * 16 + np],     wv, a0);
            a1  = ffma2(s_f12[c * 16 + np + 1], wv, a1);
            r0  = ffma2(s_f21[c * 16 + np],     wv, r0);
            r1v = ffma2(s_f21[c * 16 + np + 1], wv, r1v);
        }
        float v1, v2;
        int q = (b * N + n0 + np) * 64 + m;
        unpk2(v1, v2, a0);  q1o[q] = v1;      q2o[q] = v2;
        unpk2(v1, v2, a1);  q1o[q + 64] = v1; q2o[q + 64] = v2;
        unpk2(v1, v2, r0);  r1o[q] = v1;      r2o[q] = v2;
        unpk2(v1, v2, r1v); r1o[q + 64] = v1; r2o[q + 64] = v2;
        return;
    }

    if (blockIdx.x >= N / 32) return;
    ulonglong2* s_t0 = (ulonglong2*)smraw;
    ulonglong2* s_t1 = s_t0 + (TILE / 2);
    const int dir = blockIdx.z;
    const float* q  = dir ? pc2 : pc1;
    const float* db = dir ? pc1 : pc2;
    int* oi = dir ? i21 : i12;
    const int b = blockIdx.y;
    const int warp = tid >> 5, lane = tid & 31;
    const int nA = blockIdx.x * 32 + warp * 2;
    const int nB = nA + 1;
    const float* qb = q + b * 3 * N;
    const ull m2qAx = dup2(-2.0f * qb[nA]);
    const ull m2qAy = dup2(-2.0f * qb[N + nA]);
    const ull m2qAz = dup2(-2.0f * qb[2 * N + nA]);
    const ull m2qBx = dup2(-2.0f * qb[nB]);
    const ull m2qBy = dup2(-2.0f * qb[N + nB]);
    const ull m2qBz = dup2(-2.0f * qb[2 * N + nB]);
    const float* dbb = db + b * 3 * N;

    float bd = 3.0e38f;
    int bi = 0;
    float tauA = 3.0e38f, tauB = 3.0e38f;
    const bool halfA = (lane < 16);

    for (int t = 0; t < N; t += TILE) {
        __syncthreads();
        const float2* gx = (const float2*)(dbb + t);
        const float2* gy = (const float2*)(dbb + N + t);
        const float2* gz = (const float2*)(dbb + 2 * N + t);
        for (int i = tid; i < TILE / 2; i += 512) {
            float2 x = gx[i], y = gy[i], z = gz[i];
            float w0 = x.x * x.x + y.x * y.x + z.x * z.x;
            float w1 = x.y * x.y + y.y * y.y + z.y * z.y;
            ulonglong2 A, B;
            A.x = *(const ull*)&x; A.y = *(const ull*)&y;
            B.x = *(const ull*)&z; B.y = pk2(w0, w1);
            s_t0[i] = A; s_t1[i] = B;
        }
        __syncthreads();
        for (int p = 0; p < TILE / 2; p += 32) {
            ulonglong2 t0 = s_t0[p + lane];
            ulonglong2 t1 = s_t1[p + lane];
            ull dA = ffma2(t0.x, m2qAx, t1.y);
            dA = ffma2(t0.y, m2qAy, dA);
            dA = ffma2(t1.x, m2qAz, dA);
            ull dB = ffma2(t0.x, m2qBx, t1.y);
            dB = ffma2(t0.y, m2qBy, dB);
            dB = ffma2(t1.x, m2qBz, dB);
            float dA0, dA1, dB0, dB1;
            unpk2(dA0, dA1, dA);
            unpk2(dB0, dB1, dB);
            bool hit = (fminf(dA0, dA1) < tauA) | (fminf(dB0, dB1) < tauB);
            if (__ballot_sync(FULLMASK, hit)) {
                const int base = t + 2 * p;
                unsigned mA0 = __ballot_sync(FULLMASK, dA0 < tauA);
                unsigned mA1 = __ballot_sync(FULLMASK, dA1 < tauA);
                unsigned mB0 = __ballot_sync(FULLMASK, dB0 < tauB);
                unsigned mB1 = __ballot_sync(FULLMASK, dB1 < tauB);
                unsigned mm0 = halfA ? mA0 : mB0;
                unsigned mm1 = halfA ? mA1 : mB1;
                while (__ballot_sync(FULLMASK, mm0 != 0)) {
                    int src = __ffs(mm0) - 1;
                    float vA = __shfl_sync(FULLMASK, dA0, src & 31);
                    float vB = __shfl_sync(FULLMASK, dB0, src & 31);
                    float dd = halfA ? vA : vB;
                    float up  = __shfl_up_sync(FULLMASK, bd, 1, 16);
                    int   upi = __shfl_up_sync(FULLMASK, bi, 1, 16);
                    if ((lane & 15) == 0) up = -3.0e38f;
                    if (mm0 && bd > dd) {
                        bool tk = up > dd;
                        bd = tk ? up : dd;
                        bi = tk ? upi : base + 2 * src;
                    }
                    mm0 &= mm0 - 1;
                }
                while (__ballot_sync(FULLMASK, mm1 != 0)) {
                    int src = __ffs(mm1) - 1;
                    float vA = __shfl_sync(FULLMASK, dA1, src & 31);
                    float vB = __shfl_sync(FULLMASK, dB1, src & 31);
                    float dd = halfA ? vA : vB;
                    float up  = __shfl_up_sync(FULLMASK, bd, 1, 16);
                    int   upi = __shfl_up_sync(FULLMASK, bi, 1, 16);
                    if ((lane & 15) == 0) up = -3.0e38f;
                    if (mm1 && bd > dd) {
                        bool tk = up > dd;
                        bd = tk ? up : dd;
                        bi = tk ? upi : base + 2 * src + 1;
                    }
                    mm1 &= mm1 - 1;
                }
                tauA = __shfl_sync(FULLMASK, bd, 15);
                tauB = __shfl_sync(FULLMASK, bd, 31);
            }
        }
    }
    const int nOut = halfA ? nA : nB;
    oi[((b * N) + nOut) * 16 + (lane & 15)] = bi;
}

// ================= tf32 tensor-core cross (+ optional fp32 final-linear epilogue) =================
// block = 256 threads = 8 warps; each warp: 4 queries, m16n8k8 tf32 MMA per query.
// smem (uint words):
#define U_W1 0          // 64*68
#define U_W2 4352       // 64*68
#define U_W3 8704       // 64*68 (fp32, epilogue)
#define U_PWT 13056     // 192
#define U_PB  13248     // 64
#define U_B1  13312     // 64
#define U_B2  13376     // 64
#define U_B3  13440     // 64
#define U_H   13504     // 8 warps * 16*68 = 8704
#define U_POOL 22208    // 8 warps * 256 = 2048
#define SMEM_WORDS 24256

template <int NL, int EPI>
__global__ __launch_bounds__(256) void cross_kernel(
    const int* __restrict__ iA, const int* __restrict__ iB,
    const float* __restrict__ xA, const float* __restrict__ xB,
    const float* __restrict__ p1A, const float* __restrict__ p2A,
    const float* __restrict__ p1B, const float* __restrict__ p2B,
    const float* __restrict__ posw, const float* __restrict__ posb,
    const float* __restrict__ w1, const float* __restrict__ b1,
    const float* __restrict__ w2, const float* __restrict__ b2,
    const float* __restrict__ w3A, const float* __restrict__ b3A,
    const float* __restrict__ w3B, const float* __restrict__ b3B,
    float* __restrict__ obnA, float* __restrict__ obnB,
    float* __restrict__ ocnA, float* __restrict__ ocnB)
{
    extern __shared__ uint smu[];
    uint*  s_w1u = smu + U_W1;
    uint*  s_w2u = smu + U_W2;
    float* s_w3  = (float*)(smu + U_W3);
    float* s_pwt = (float*)(smu + U_PWT);
    float* s_pb  = (float*)(smu + U_PB);
    float* s_b1  = (float*)(smu + U_B1);
    float* s_b2  = (float*)(smu + U_B2);
    float* s_b3  = (float*)(smu + U_B3);
    uint*  s_hall = smu + U_H;
    float* s_pool = (float*)(smu + U_POOL);

    const int dir = blockIdx.y;
    const int* idx = dir ? iB : iA;
    const float* xyz1 = dir ? xB : xA;
    const float* xyz2 = dir ? xA : xB;
    const float* p1 = dir ? p1B : p1A;
    const float* p2 = dir ? p2B : p2A;
    const float* w3 = dir ? w3B : w3A;
    const float* b3 = dir ? b3B : b3A;
    float* obn = dir ? obnB : obnA;
    float* ocn = dir ? ocnB : ocnA;

    const int tid = threadIdx.x;
    for (int i = tid; i < 4096; i += 256) {
        int m = i >> 6, c = i & 63;
        s_w1u[m * 68 + c] = tf32r(w1[i]);
        if (NL == 2) s_w2u[m * 68 + c] = tf32r(w2[i]);
        if (EPI)     s_w3[m * 68 + c] = w3[i];
    }
    if (tid < 192) s_pwt[tid] = posw[(tid & 63) * 3 + (tid >> 6)];
    if (tid < 64) {
        s_pb[tid] = posb[tid];
        s_b1[tid] = b1[tid];
        if (NL == 2) s_b2[tid] = b2[tid];
        if (EPI)     s_b3[tid] = b3[tid];
    }
    __syncthreads();

    const int warp = tid >> 5, lane = tid & 31;
    const int g = lane >> 2, t = lane & 3;
    uint*  s_h  = s_hall + warp * 1088;   // 16 rows * 68
    float* s_pw = s_pool + warp * 256;    // 4 queries * 64
    const int wq0 = (blockIdx.x * 8 + warp) * 4;

    const float pw0a = s_pwt[lane],      pw1a = s_pwt[64 + lane],  pw2a = s_pwt[128 + lane];
    const float pw0b = s_pwt[lane + 32], pw1b = s_pwt[96 + lane],  pw2b = s_pwt[160 + lane];
    const float pba = s_pb[lane], pbb = s_pb[lane + 32];

    for (int qi = 0; qi < 4; qi++) {
        const int q = wq0 + qi;
        const int b = q >> 13, n = q & (N - 1);
        const int myidx = idx[q * 16 + (lane & 15)];
        const float p1a = p1[q * 64 + lane];
        const float p1b = p1[q * 64 + 32 + lane];
        const float* x1b = xyz1 + b * 3 * N;
        const float qx = x1b[n], qy = x1b[N + n], qz = x1b[2 * N + n];
        const float* x2b = xyz2 + b * 3 * N;
        const float nx = x2b[myidx], ny = x2b[N + myidx], nz = x2b[2 * N + myidx];

        // gather: h[k][c] = leaky(g2 + p1 + posf), tf32-rounded
        #pragma unroll
        for (int k = 0; k < 16; k++) {
            int j = __shfl_sync(FULLMASK, myidx, k);
            float dx = __shfl_sync(FULLMASK, nx, k) - qx;
            float dy = __shfl_sync(FULLMASK, ny, k) - qy;
            float dz = __shfl_sync(FULLMASK, nz, k) - qz;
            const float* p2r = p2 + ((size_t)((b << 13) + j)) * 64;
            float ga = p2r[lane], gb = p2r[lane + 32];
            float pa = pba + dx * pw0a + dy * pw1a + dz * pw2a;
            float pb = pbb + dx * pw0b + dy * pw1b + dz * pw2b;
            s_h[k * 68 + lane]      = tf32r(leaky(ga + p1a + pa));
            s_h[k * 68 + 32 + lane] = tf32r(leaky(gb + p1b + pb));
        }
        __syncwarp();

        float d[8][4];
        // ----- layer 1 (bias in accumulator) -----
        #pragma unroll
        for (int nt = 0; nt < 8; nt++) {
            float2 bv = *(const float2*)&s_b1[nt * 8 + t * 2];
            d[nt][0] = bv.x; d[nt][1] = bv.y; d[nt][2] = bv.x; d[nt][3] = bv.y;
        }
        #pragma unroll
        for (int ks = 0; ks < 8; ks++) {
            uint a0 = s_h[g * 68 + ks * 8 + t];
            uint a1 = s_h[(g + 8) * 68 + ks * 8 + t];
            uint a2 = s_h[g * 68 + ks * 8 + t + 4];
            uint a3 = s_h[(g + 8) * 68 + ks * 8 + t + 4];
            #pragma unroll
            for (int nt = 0; nt < 8; nt++) {
                uint wb0 = s_w1u[(nt * 8 + g) * 68 + ks * 8 + t];
                uint wb1 = s_w1u[(nt * 8 + g) * 68 + ks * 8 + t + 4];
                mma_tf32(d[nt], a0, a1, a2, a3, wb0, wb1);
            }
        }

        if (NL == 2) {
            __syncwarp();
            #pragma unroll
            for (int nt = 0; nt < 8; nt++) {
                int c0 = nt * 8 + t * 2;
                s_h[g * 68 + c0]           = tf32r(leaky(d[nt][0]));
                s_h[g * 68 + c0 + 1]       = tf32r(leaky(d[nt][1]));
                s_h[(g + 8) * 68 + c0]     = tf32r(leaky(d[nt][2]));
                s_h[(g + 8) * 68 + c0 + 1] = tf32r(leaky(d[nt][3]));
            }
            __syncwarp();
            #pragma unroll
            for (int nt = 0; nt < 8; nt++) {
                float2 bv = *(const float2*)&s_b2[nt * 8 + t * 2];
                d[nt][0] = bv.x; d[nt][1] = bv.y; d[nt][2] = bv.x; d[nt][3] = bv.y;
            }
            #pragma unroll
            for (int ks = 0; ks < 8; ks++) {
                uint a0 = s_h[g * 68 + ks * 8 + t];
                uint a1 = s_h[(g + 8) * 68 + ks * 8 + t];
                uint a2 = s_h[g * 68 + ks * 8 + t + 4];
                uint a3 = s_h[(g + 8) * 68 + ks * 8 + t + 4];
                #pragma unroll
                for (int nt = 0; nt < 8; nt++) {
                    uint wb0 = s_w2u[(nt * 8 + g) * 68 + ks * 8 + t];
                    uint wb1 = s_w2u[(nt * 8 + g) * 68 + ks * 8 + t + 4];
                    mma_tf32(d[nt], a0, a1, a2, a3, wb0, wb1);
                }
            }
        }

        // maxpool over the 16 rows (k), then leaky (monotonic)
        #pragma unroll
        for (int nt = 0; nt < 8; nt++) {
            float u0 = fmaxf(d[nt][0], d[nt][2]);
            float u1 = fmaxf(d[nt][1], d[nt][3]);
            u0 = fmaxf(u0, __shfl_xor_sync(FULLMASK, u0, 4));
            u1 = fmaxf(u1, __shfl_xor_sync(FULLMASK, u1, 4));
            u0 = fmaxf(u0, __shfl_xor_sync(FULLMASK, u0, 8));
            u1 = fmaxf(u1, __shfl_xor_sync(FULLMASK, u1, 8));
            u0 = fmaxf(u0, __shfl_xor_sync(FULLMASK, u0, 16));
            u1 = fmaxf(u1, __shfl_xor_sync(FULLMASK, u1, 16));
            if (nt == g) {
                if (EPI) {
                    s_pw[qi * 64 + g * 8 + t * 2]     = leaky(u0);
                    s_pw[qi * 64 + g * 8 + t * 2 + 1] = leaky(u1);
                } else {
                    ocn[((b * 64) + g * 8 + t * 2) * N + n]     = leaky(u0);
                    ocn[((b * 64) + g * 8 + t * 2 + 1) * N + n] = leaky(u1);
                }
            }
        }
        __syncwarp();
    }

    if (EPI) {
        // fp32 final linear: lane owns channels (lane, lane+32); 4 queries
        float acc[4][2];
        #pragma unroll
        for (int q4 = 0; q4 < 4; q4++) { acc[q4][0] = s_b3[lane]; acc[q4][1] = s_b3[lane + 32]; }
        #pragma unroll
        for (int jb = 0; jb < 16; jb++) {
            float4 wa = *(const float4*)&s_w3[lane * 68 + jb * 4];
            float4 wb = *(const float4*)&s_w3[(lane + 32) * 68 + jb * 4];
            #pragma unroll
            for (int q4 = 0; q4 < 4; q4++) {
                float4 hv = *(const float4*)&s_pw[q4 * 64 + jb * 4];
                acc[q4][0] += hv.x * wa.x + hv.y * wa.y + hv.z * wa.z + hv.w * wa.w;
                acc[q4][1] += hv.x * wb.x + hv.y * wb.y + hv.z * wb.z + hv.w * wb.w;
            }
        }
        #pragma unroll
        for (int q4 = 0; q4 < 4; q4++) {
            const int q = wq0 + q4;
            const int b = q >> 13, n = q & (N - 1);
            obn[q * 64 + lane]      = acc[q4][0];
            obn[q * 64 + 32 + lane] = acc[q4][1];
            ocn[((b * 64) + lane) * N + n]      = acc[q4][0];
            ocn[((b * 64) + lane + 32) * N + n] = acc[q4][1];
        }
    }
}

// ---------------- launch ----------------
extern "C" void kernel_launch(void* const* d_in, const int* in_sizes, int n_in,
                              void* d_out, int out_size)
{
    const float* pc1     = (const float*)d_in[0];
    const float* pc2     = (const float*)d_in[1];
    const float* feat1   = (const float*)d_in[2];
    const float* feat2   = (const float*)d_in[3];
    const float* t11_w   = (const float*)d_in[4];
    const float* t11_b   = (const float*)d_in[5];
    const float* t22_w   = (const float*)d_in[6];
    const float* t22_b   = (const float*)d_in[7];
    const float* pos1_w  = (const float*)d_in[8];
    const float* pos1_b  = (const float*)d_in[9];
    const float* mlp1_w1 = (const float*)d_in[10];
    const float* mlp1_b1 = (const float*)d_in[11];
    const float* mlp1_w2 = (const float*)d_in[12];
    const float* mlp1_b2 = (const float*)d_in[13];
    const float* t1_w    = (const float*)d_in[14];
    const float* t1_b    = (const float*)d_in[15];
    const float* t2_w    = (const float*)d_in[16];
    const float* t2_b    = (const float*)d_in[17];
    const float* pos2_w  = (const float*)d_in[18];
    const float* pos2_b  = (const float*)d_in[19];
    const float* mlp2_w1 = (const float*)d_in[20];
    const float* mlp2_b1 = (const float*)d_in[21];
    float* out = (float*)d_out;

    float *q1, *q2, *r1, *r2, *f1, *f2;
    int *i12, *i21;
    cudaGetSymbolAddress((void**)&q1, g_q1);
    cudaGetSymbolAddress((void**)&q2, g_q2);
    cudaGetSymbolAddress((void**)&r1, g_r1);
    cudaGetSymbolAddress((void**)&r2, g_r2);
    cudaGetSymbolAddress((void**)&f1, g_f1);
    cudaGetSymbolAddress((void**)&f2, g_f2);
    cudaGetSymbolAddress((void**)&i12, g_i12);
    cudaGetSymbolAddress((void**)&i21, g_i21);

    // fused KNN (z=0,1; 32KB tiles) + transforms (z=2; 48KB)
    const size_t smem_kt = 49152;
    cudaFuncSetAttribute(knn_transform_kernel, cudaFuncAttributeMaxDynamicSharedMemorySize, (int)smem_kt);
    knn_transform_kernel<<<dim3(N / 16, BB, 3), 512, smem_kt>>>(
        pc1, pc2, i12, i21,
        feat1, feat2, t11_w, t11_b, t22_w, t22_b,
        q1, q2, r1, r2);

    const size_t smem = (size_t)SMEM_WORDS * 4;
    cudaFuncSetAttribute(cross_kernel<2,1>, cudaFuncAttributeMaxDynamicSharedMemorySize, (int)smem);
    cudaFuncSetAttribute(cross_kernel<1,0>, cudaFuncAttributeMaxDynamicSharedMemorySize, (int)smem);

    // cross 1 & 2 fused (grid.y = direction) with fp32 final-linear epilogue
    cross_kernel<2,1><<<dim3(BB * N / 32, 2), 256, smem>>>(
        i12, i21, pc1, pc2,
        q1, q2, r1, r2,
        pos1_w, pos1_b, mlp1_w1, mlp1_b1, mlp1_w2, mlp1_b2,
        t1_w, t1_b, t2_w, t2_b,
        f1, f2, out, out + (size_t)BB * 64 * N);

    // cross 3 (1 mlp layer), transposed direct write to output region 2
    cross_kernel<1,0><<<dim3(BB * N / 32, 1), 256, smem>>>(
        i12, i12, pc1, pc2,
        f1, f2, f1, f2,
        pos2_w, pos2_b, mlp2_w1, mlp2_b1, mlp2_w1, mlp2_b1,
        mlp2_w1, mlp2_b1, mlp2_w1, mlp2_b1,
        out + (size_t)2 * BB * 64 * N, out + (size_t)2 * BB * 64 * N,
        out + (size_t)2 * BB * 64 * N, out + (size_t)2 * BB * 64 * N);
}

// round 9
// speedup vs baseline: 1.4777x; 1.0232x over previous
#include <cuda_runtime.h>

#define N 8192
#define BB 2
#define CH 64
#define KNB 16
#define FULLMASK 0xffffffffu
typedef unsigned long long ull;
typedef unsigned int uint;

// ---------------- scratch (static device globals; no allocation) ----------------
__device__ float g_q1[BB*N*CH];
__device__ float g_q2[BB*N*CH];
__device__ float g_r1[BB*N*CH];
__device__ float g_r2[BB*N*CH];
__device__ float g_f1[BB*N*CH];
__device__ float g_f2[BB*N*CH];
__device__ int   g_i12[BB*N*KNB];
__device__ int   g_i21[BB*N*KNB];

__device__ __forceinline__ float leaky(float x) { return fmaxf(x, 0.1f * x); }

// ---------------- packed f32x2 helpers (knn/transform) ----------------
__device__ __forceinline__ ull ffma2(ull a, ull b, ull c) {
    ull d; asm("fma.rn.f32x2 %0, %1, %2, %3;" : "=l"(d) : "l"(a), "l"(b), "l"(c)); return d;
}
__device__ __forceinline__ ull pk2(float x, float y) {
    ull r; asm("mov.b64 %0, {%1, %2};" : "=l"(r) : "f"(x), "f"(y)); return r;
}
__device__ __forceinline__ ull dup2(float x) {
    ull r; asm("mov.b64 %0, {%1, %1};" : "=l"(r) : "f"(x)); return r;
}
__device__ __forceinline__ void unpk2(float& lo, float& hi, ull v) {
    asm("mov.b64 {%0, %1}, %2;" : "=f"(lo), "=f"(hi) : "l"(v));
}

// ---------------- tf32 / mma / ldmatrix helpers (cross) ----------------
__device__ __forceinline__ uint tf32r(float x) {
    uint u; asm("cvt.rna.tf32.f32 %0, %1;" : "=r"(u) : "f"(x)); return u;
}
__device__ __forceinline__ void mma_tf32(float* d, uint a0, uint a1, uint a2, uint a3,
                                         uint b0, uint b1) {
    asm volatile(
        "mma.sync.aligned.m16n8k8.row.col.f32.tf32.tf32.f32 "
        "{%0,%1,%2,%3}, {%4,%5,%6,%7}, {%8,%9}, {%0,%1,%2,%3};"
        : "+f"(d[0]), "+f"(d[1]), "+f"(d[2]), "+f"(d[3])
        : "r"(a0), "r"(a1), "r"(a2), "r"(a3), "r"(b0), "r"(b1));
}
__device__ __forceinline__ void ldsm_x4(uint& r0, uint& r1, uint& r2, uint& r3, uint a) {
    asm volatile("ldmatrix.sync.aligned.m8n8.x4.shared.b16 {%0,%1,%2,%3}, [%4];"
        : "=r"(r0), "=r"(r1), "=r"(r2), "=r"(r3) : "r"(a));
}
__device__ __forceinline__ void ldsm_x2(uint& r0, uint& r1, uint a) {
    asm volatile("ldmatrix.sync.aligned.m8n8.x2.shared.b16 {%0,%1}, [%2];"
        : "=r"(r0), "=r"(r1) : "r"(a));
}

// ================= fused KNN (z=0,1; 2 queries/warp) + 4-way transform (z=2) =================
#define TILE 2048   // 32KB tile -> 4 blocks/SM

__global__ __launch_bounds__(512, 4) void knn_transform_kernel(
    const float* __restrict__ pc1, const float* __restrict__ pc2,
    int* __restrict__ i12, int* __restrict__ i21,
    const float* __restrict__ f1g, const float* __restrict__ f2g,
    const float* __restrict__ w11, const float* __restrict__ b11,
    const float* __restrict__ w22, const float* __restrict__ b22,
    float* __restrict__ q1o, float* __restrict__ q2o,
    float* __restrict__ r1o, float* __restrict__ r2o)
{
    extern __shared__ char smraw[];
    const int tid = threadIdx.x;

    if (blockIdx.z == 2) {
        ull* s_wp  = (ull*)smraw;
        ull* s_f12 = s_wp + 4096;
        ull* s_f21 = s_f12 + 1024;
        const int b = blockIdx.y, n0 = blockIdx.x * 16;
        for (int i = tid; i < 4096; i += 512) {
            int m = i >> 6, c = i & 63;
            s_wp[c * 64 + m] = pk2(w11[i], w22[i]);
        }
        for (int i = tid; i < 1024; i += 512) {
            int c = i >> 4, np = i & 15;
            float a = f1g[(b * 64 + c) * N + n0 + np];
            float d = f2g[(b * 64 + c) * N + n0 + np];
            s_f12[i] = pk2(a, d);
            s_f21[i] = pk2(d, a);
        }
        __syncthreads();
        const int m = tid & 63, grp = tid >> 6;
        ull bq = pk2(b11[m], b22[m]);
        ull a0 = bq, a1 = bq, r0 = bq, r1v = bq;
        const int np = grp * 2;
        #pragma unroll 8
        for (int c = 0; c < 64; c++) {
            ull wv = s_wp[c * 64 + m];
            a0  = ffma2(s_f12[c * 16 + np],     wv, a0);
            a1  = ffma2(s_f12[c * 16 + np + 1], wv, a1);
            r0  = ffma2(s_f21[c * 16 + np],     wv, r0);
            r1v = ffma2(s_f21[c * 16 + np + 1], wv, r1v);
        }
        float v1, v2;
        int q = (b * N + n0 + np) * 64 + m;
        unpk2(v1, v2, a0);  q1o[q] = v1;      q2o[q] = v2;
        unpk2(v1, v2, a1);  q1o[q + 64] = v1; q2o[q + 64] = v2;
        unpk2(v1, v2, r0);  r1o[q] = v1;      r2o[q] = v2;
        unpk2(v1, v2, r1v); r1o[q + 64] = v1; r2o[q + 64] = v2;
        return;
    }

    if (blockIdx.x >= N / 32) return;
    ulonglong2* s_t0 = (ulonglong2*)smraw;
    ulonglong2* s_t1 = s_t0 + (TILE / 2);
    const int dir = blockIdx.z;
    const float* q  = dir ? pc2 : pc1;
    const float* db = dir ? pc1 : pc2;
    int* oi = dir ? i21 : i12;
    const int b = blockIdx.y;
    const int warp = tid >> 5, lane = tid & 31;
    const int nA = blockIdx.x * 32 + warp * 2;
    const int nB = nA + 1;
    const float* qb = q + b * 3 * N;
    const ull m2qAx = dup2(-2.0f * qb[nA]);
    const ull m2qAy = dup2(-2.0f * qb[N + nA]);
    const ull m2qAz = dup2(-2.0f * qb[2 * N + nA]);
    const ull m2qBx = dup2(-2.0f * qb[nB]);
    const ull m2qBy = dup2(-2.0f * qb[N + nB]);
    const ull m2qBz = dup2(-2.0f * qb[2 * N + nB]);
    const float* dbb = db + b * 3 * N;

    float bd = 3.0e38f;
    int bi = 0;
    float tauA = 3.0e38f, tauB = 3.0e38f;
    const bool halfA = (lane < 16);

    for (int t = 0; t < N; t += TILE) {
        __syncthreads();
        const float2* gx = (const float2*)(dbb + t);
        const float2* gy = (const float2*)(dbb + N + t);
        const float2* gz = (const float2*)(dbb + 2 * N + t);
        for (int i = tid; i < TILE / 2; i += 512) {
            float2 x = gx[i], y = gy[i], z = gz[i];
            float w0 = x.x * x.x + y.x * y.x + z.x * z.x;
            float w1 = x.y * x.y + y.y * y.y + z.y * z.y;
            ulonglong2 A, B;
            A.x = *(const ull*)&x; A.y = *(const ull*)&y;
            B.x = *(const ull*)&z; B.y = pk2(w0, w1);
            s_t0[i] = A; s_t1[i] = B;
        }
        __syncthreads();
        for (int p = 0; p < TILE / 2; p += 32) {
            ulonglong2 t0 = s_t0[p + lane];
            ulonglong2 t1 = s_t1[p + lane];
            ull dA = ffma2(t0.x, m2qAx, t1.y);
            dA = ffma2(t0.y, m2qAy, dA);
            dA = ffma2(t1.x, m2qAz, dA);
            ull dB = ffma2(t0.x, m2qBx, t1.y);
            dB = ffma2(t0.y, m2qBy, dB);
            dB = ffma2(t1.x, m2qBz, dB);
            float dA0, dA1, dB0, dB1;
            unpk2(dA0, dA1, dA);
            unpk2(dB0, dB1, dB);
            bool hit = (fminf(dA0, dA1) < tauA) | (fminf(dB0, dB1) < tauB);
            if (__ballot_sync(FULLMASK, hit)) {
                const int base = t + 2 * p;
                unsigned mA0 = __ballot_sync(FULLMASK, dA0 < tauA);
                unsigned mA1 = __ballot_sync(FULLMASK, dA1 < tauA);
                unsigned mB0 = __ballot_sync(FULLMASK, dB0 < tauB);
                unsigned mB1 = __ballot_sync(FULLMASK, dB1 < tauB);
                unsigned mm0 = halfA ? mA0 : mB0;
                unsigned mm1 = halfA ? mA1 : mB1;
                // element-0 candidates (warp-uniform trip count, no per-trip ballot)
                int n0it = max(__popc(mA0), __popc(mB0));
                for (int it = 0; it < n0it; it++) {
                    int src = __ffs(mm0) - 1;
                    float vA = __shfl_sync(FULLMASK, dA0, src & 31);
                    float vB = __shfl_sync(FULLMASK, dB0, src & 31);
                    float dd = halfA ? vA : vB;
                    float up  = __shfl_up_sync(FULLMASK, bd, 1, 16);
                    int   upi = __shfl_up_sync(FULLMASK, bi, 1, 16);
                    if ((lane & 15) == 0) up = -3.0e38f;
                    if (mm0 && bd > dd) {
                        bool tk = up > dd;
                        bd = tk ? up : dd;
                        bi = tk ? upi : base + 2 * src;
                    }
                    mm0 &= mm0 - 1;
                }
                // element-1 candidates
                int n1it = max(__popc(mA1), __popc(mB1));
                for (int it = 0; it < n1it; it++) {
                    int src = __ffs(mm1) - 1;
                    float vA = __shfl_sync(FULLMASK, dA1, src & 31);
                    float vB = __shfl_sync(FULLMASK, dB1, src & 31);
                    float dd = halfA ? vA : vB;
                    float up  = __shfl_up_sync(FULLMASK, bd, 1, 16);
                    int   upi = __shfl_up_sync(FULLMASK, bi, 1, 16);
                    if ((lane & 15) == 0) up = -3.0e38f;
                    if (mm1 && bd > dd) {
                        bool tk = up > dd;
                        bd = tk ? up : dd;
                        bi = tk ? upi : base + 2 * src + 1;
                    }
                    mm1 &= mm1 - 1;
                }
                tauA = __shfl_sync(FULLMASK, bd, 15);
                tauB = __shfl_sync(FULLMASK, bd, 31);
            }
        }
    }
    const int nOut = halfA ? nA : nB;
    oi[((b * N) + nOut) * 16 + (lane & 15)] = bi;
}

// ================= tf32 tensor-core cross (+ optional fp32 final-linear epilogue) =================
// block = 256 threads = 8 warps; each warp: 4 queries, m16n8k8 tf32 MMA per query.
// smem (uint words):
#define U_W1 0          // 64*68
#define U_W2 4352       // 64*68
#define U_W3 8704       // 64*68 (fp32, epilogue)
#define U_PWT 13056     // 192
#define U_PB  13248     // 64
#define U_B1  13312     // 64
#define U_B2  13376     // 64
#define U_B3  13440     // 64
#define U_H   13504     // 8 warps * 16*68 = 8704
#define U_POOL 22208    // 8 warps * 256 = 2048
#define SMEM_WORDS 24256

template <int NL, int EPI>
__global__ __launch_bounds__(256) void cross_kernel(
    const int* __restrict__ iA, const int* __restrict__ iB,
    const float* __restrict__ xA, const float* __restrict__ xB,
    const float* __restrict__ p1A, const float* __restrict__ p2A,
    const float* __restrict__ p1B, const float* __restrict__ p2B,
    const float* __restrict__ posw, const float* __restrict__ posb,
    const float* __restrict__ w1, const float* __restrict__ b1,
    const float* __restrict__ w2, const float* __restrict__ b2,
    const float* __restrict__ w3A, const float* __restrict__ b3A,
    const float* __restrict__ w3B, const float* __restrict__ b3B,
    float* __restrict__ obnA, float* __restrict__ obnB,
    float* __restrict__ ocnA, float* __restrict__ ocnB)
{
    extern __shared__ uint smu[];
    uint*  s_w1u = smu + U_W1;
    uint*  s_w2u = smu + U_W2;
    float* s_w3  = (float*)(smu + U_W3);
    float* s_pwt = (float*)(smu + U_PWT);
    float* s_pb  = (float*)(smu + U_PB);
    float* s_b1  = (float*)(smu + U_B1);
    float* s_b2  = (float*)(smu + U_B2);
    float* s_b3  = (float*)(smu + U_B3);
    uint*  s_hall = smu + U_H;
    float* s_pool = (float*)(smu + U_POOL);

    const int dir = blockIdx.y;
    const int* idx = dir ? iB : iA;
    const float* xyz1 = dir ? xB : xA;
    const float* xyz2 = dir ? xA : xB;
    const float* p1 = dir ? p1B : p1A;
    const float* p2 = dir ? p2B : p2A;
    const float* w3 = dir ? w3B : w3A;
    const float* b3 = dir ? b3B : b3A;
    float* obn = dir ? obnB : obnA;
    float* ocn = dir ? ocnB : ocnA;

    const int tid = threadIdx.x;
    for (int i = tid; i < 4096; i += 256) {
        int m = i >> 6, c = i & 63;
        s_w1u[m * 68 + c] = tf32r(w1[i]);
        if (NL == 2) s_w2u[m * 68 + c] = tf32r(w2[i]);
        if (EPI)     s_w3[m * 68 + c] = w3[i];
    }
    if (tid < 192) s_pwt[tid] = posw[(tid & 63) * 3 + (tid >> 6)];
    if (tid < 64) {
        s_pb[tid] = posb[tid];
        s_b1[tid] = b1[tid];
        if (NL == 2) s_b2[tid] = b2[tid];
        if (EPI)     s_b3[tid] = b3[tid];
    }
    __syncthreads();

    const int warp = tid >> 5, lane = tid & 31;
    const int g = lane >> 2, t = lane & 3;
    uint*  s_h  = s_hall + warp * 1088;   // 16 rows * 68
    float* s_pw = s_pool + warp * 256;    // 4 queries * 64
    const int wq0 = (blockIdx.x * 8 + warp) * 4;

    // ldmatrix per-lane bases
    const int r8 = lane & 7, q8 = lane >> 3;
    const int rowA = r8 + ((q8 >> 1) << 3);
    const int cofA = (q8 & 1) * 4;
    const uint aAddr = (uint)__cvta_generic_to_shared(s_h + rowA * 68 + cofA);
    const int rowB = r8, cofB = (q8 & 1) * 4;
    const uint b1Addr = (uint)__cvta_generic_to_shared(s_w1u + rowB * 68 + cofB);
    const uint b2Addr = (uint)__cvta_generic_to_shared(s_w2u + rowB * 68 + cofB);

    const float pw0a = s_pwt[lane],      pw1a = s_pwt[64 + lane],  pw2a = s_pwt[128 + lane];
    const float pw0b = s_pwt[lane + 32], pw1b = s_pwt[96 + lane],  pw2b = s_pwt[160 + lane];
    const float pba = s_pb[lane], pbb = s_pb[lane + 32];

    for (int qi = 0; qi < 4; qi++) {
        const int q = wq0 + qi;
        const int b = q >> 13, n = q & (N - 1);
        const int myidx = idx[q * 16 + (lane & 15)];
        const float p1a = p1[q * 64 + lane];
        const float p1b = p1[q * 64 + 32 + lane];
        const float* x1b = xyz1 + b * 3 * N;
        const float qx = x1b[n], qy = x1b[N + n], qz = x1b[2 * N + n];
        const float* x2b = xyz2 + b * 3 * N;
        const float nx = x2b[myidx], ny = x2b[N + myidx], nz = x2b[2 * N + myidx];

        // gather: h[k][c] = leaky(g2 + p1 + posf), tf32-rounded
        #pragma unroll
        for (int k = 0; k < 16; k++) {
            int j = __shfl_sync(FULLMASK, myidx, k);
            float dx = __shfl_sync(FULLMASK, nx, k) - qx;
            float dy = __shfl_sync(FULLMASK, ny, k) - qy;
            float dz = __shfl_sync(FULLMASK, nz, k) - qz;
            const float* p2r = p2 + ((size_t)((b << 13) + j)) * 64;
            float ga = p2r[lane], gb = p2r[lane + 32];
            float pa = pba + dx * pw0a + dy * pw1a + dz * pw2a;
            float pb = pbb + dx * pw0b + dy * pw1b + dz * pw2b;
            s_h[k * 68 + lane]      = tf32r(leaky(ga + p1a + pa));
            s_h[k * 68 + 32 + lane] = tf32r(leaky(gb + p1b + pb));
        }
        __syncwarp();

        float d[8][4];
        // ----- layer 1 (bias in accumulator) -----
        #pragma unroll
        for (int nt = 0; nt < 8; nt++) {
            float2 bv = *(const float2*)&s_b1[nt * 8 + t * 2];
            d[nt][0] = bv.x; d[nt][1] = bv.y; d[nt][2] = bv.x; d[nt][3] = bv.y;
        }
        #pragma unroll
        for (int ks = 0; ks < 8; ks++) {
            uint f0, f1, f2, f3;                 // = a0, a2, a1, a3
            ldsm_x4(f0, f1, f2, f3, aAddr + ks * 32);
            #pragma unroll
            for (int nt = 0; nt < 8; nt++) {
                uint b0, b1v;
                ldsm_x2(b0, b1v, b1Addr + (nt * 8 * 68 + ks * 8) * 4);
                mma_tf32(d[nt], f0, f2, f1, f3, b0, b1v);
            }
        }

        if (NL == 2) {
            __syncwarp();
            #pragma unroll
            for (int nt = 0; nt < 8; nt++) {
                int c0 = nt * 8 + t * 2;
                s_h[g * 68 + c0]           = tf32r(leaky(d[nt][0]));
                s_h[g * 68 + c0 + 1]       = tf32r(leaky(d[nt][1]));
                s_h[(g + 8) * 68 + c0]     = tf32r(leaky(d[nt][2]));
                s_h[(g + 8) * 68 + c0 + 1] = tf32r(leaky(d[nt][3]));
            }
            __syncwarp();
            #pragma unroll
            for (int nt = 0; nt < 8; nt++) {
                float2 bv = *(const float2*)&s_b2[nt * 8 + t * 2];
                d[nt][0] = bv.x; d[nt][1] = bv.y; d[nt][2] = bv.x; d[nt][3] = bv.y;
            }
            #pragma unroll
            for (int ks = 0; ks < 8; ks++) {
                uint f0, f1, f2, f3;
                ldsm_x4(f0, f1, f2, f3, aAddr + ks * 32);
                #pragma unroll
                for (int nt = 0; nt < 8; nt++) {
                    uint b0, b1v;
                    ldsm_x2(b0, b1v, b2Addr + (nt * 8 * 68 + ks * 8) * 4);
                    mma_tf32(d[nt], f0, f2, f1, f3, b0, b1v);
                }
            }
        }

        // maxpool over the 16 rows (k), then leaky (monotonic)
        #pragma unroll
        for (int nt = 0; nt < 8; nt++) {
            float u0 = fmaxf(d[nt][0], d[nt][2]);
            float u1 = fmaxf(d[nt][1], d[nt][3]);
            u0 = fmaxf(u0, __shfl_xor_sync(FULLMASK, u0, 4));
            u1 = fmaxf(u1, __shfl_xor_sync(FULLMASK, u1, 4));
            u0 = fmaxf(u0, __shfl_xor_sync(FULLMASK, u0, 8));
            u1 = fmaxf(u1, __shfl_xor_sync(FULLMASK, u1, 8));
            u0 = fmaxf(u0, __shfl_xor_sync(FULLMASK, u0, 16));
            u1 = fmaxf(u1, __shfl_xor_sync(FULLMASK, u1, 16));
            if (nt == g) {
                if (EPI) {
                    s_pw[qi * 64 + g * 8 + t * 2]     = leaky(u0);
                    s_pw[qi * 64 + g * 8 + t * 2 + 1] = leaky(u1);
                } else {
                    ocn[((b * 64) + g * 8 + t * 2) * N + n]     = leaky(u0);
                    ocn[((b * 64) + g * 8 + t * 2 + 1) * N + n] = leaky(u1);
                }
            }
        }
        __syncwarp();
    }

    if (EPI) {
        // fp32 final linear: lane owns channels (lane, lane+32); 4 queries
        float acc[4][2];
        #pragma unroll
        for (int q4 = 0; q4 < 4; q4++) { acc[q4][0] = s_b3[lane]; acc[q4][1] = s_b3[lane + 32]; }
        #pragma unroll
        for (int jb = 0; jb < 16; jb++) {
            float4 wa = *(const float4*)&s_w3[lane * 68 + jb * 4];
            float4 wb = *(const float4*)&s_w3[(lane + 32) * 68 + jb * 4];
            #pragma unroll
            for (int q4 = 0; q4 < 4; q4++) {
                float4 hv = *(const float4*)&s_pw[q4 * 64 + jb * 4];
                acc[q4][0] += hv.x * wa.x + hv.y * wa.y + hv.z * wa.z + hv.w * wa.w;
                acc[q4][1] += hv.x * wb.x + hv.y * wb.y + hv.z * wb.z + hv.w * wb.w;
            }
        }
        #pragma unroll
        for (int q4 = 0; q4 < 4; q4++) {
            const int q = wq0 + q4;
            const int b = q >> 13, n = q & (N - 1);
            obn[q * 64 + lane]      = acc[q4][0];
            obn[q * 64 + 32 + lane] = acc[q4][1];
            ocn[((b * 64) + lane) * N + n]      = acc[q4][0];
            ocn[((b * 64) + lane + 32) * N + n] = acc[q4][1];
        }
    }
}

// ---------------- launch ----------------
extern "C" void kernel_launch(void* const* d_in, const int* in_sizes, int n_in,
                              void* d_out, int out_size)
{
    const float* pc1     = (const float*)d_in[0];
    const float* pc2     = (const float*)d_in[1];
    const float* feat1   = (const float*)d_in[2];
    const float* feat2   = (const float*)d_in[3];
    const float* t11_w   = (const float*)d_in[4];
    const float* t11_b   = (const float*)d_in[5];
    const float* t22_w   = (const float*)d_in[6];
    const float* t22_b   = (const float*)d_in[7];
    const float* pos1_w  = (const float*)d_in[8];
    const float* pos1_b  = (const float*)d_in[9];
    const float* mlp1_w1 = (const float*)d_in[10];
    const float* mlp1_b1 = (const float*)d_in[11];
    const float* mlp1_w2 = (const float*)d_in[12];
    const float* mlp1_b2 = (const float*)d_in[13];
    const float* t1_w    = (const float*)d_in[14];
    const float* t1_b    = (const float*)d_in[15];
    const float* t2_w    = (const float*)d_in[16];
    const float* t2_b    = (const float*)d_in[17];
    const float* pos2_w  = (const float*)d_in[18];
    const float* pos2_b  = (const float*)d_in[19];
    const float* mlp2_w1 = (const float*)d_in[20];
    const float* mlp2_b1 = (const float*)d_in[21];
    float* out = (float*)d_out;

    float *q1, *q2, *r1, *r2, *f1, *f2;
    int *i12, *i21;
    cudaGetSymbolAddress((void**)&q1, g_q1);
    cudaGetSymbolAddress((void**)&q2, g_q2);
    cudaGetSymbolAddress((void**)&r1, g_r1);
    cudaGetSymbolAddress((void**)&r2, g_r2);
    cudaGetSymbolAddress((void**)&f1, g_f1);
    cudaGetSymbolAddress((void**)&f2, g_f2);
    cudaGetSymbolAddress((void**)&i12, g_i12);
    cudaGetSymbolAddress((void**)&i21, g_i21);

    // fused KNN (z=0,1; 32KB tiles) + transforms (z=2; 48KB)
    const size_t smem_kt = 49152;
    cudaFuncSetAttribute(knn_transform_kernel, cudaFuncAttributeMaxDynamicSharedMemorySize, (int)smem_kt);
    knn_transform_kernel<<<dim3(N / 16, BB, 3), 512, smem_kt>>>(
        pc1, pc2, i12, i21,
        feat1, feat2, t11_w, t11_b, t22_w, t22_b,
        q1, q2, r1, r2);

    const size_t smem = (size_t)SMEM_WORDS * 4;
    cudaFuncSetAttribute(cross_kernel<2,1>, cudaFuncAttributeMaxDynamicSharedMemorySize, (int)smem);
    cudaFuncSetAttribute(cross_kernel<1,0>, cudaFuncAttributeMaxDynamicSharedMemorySize, (int)smem);

    // cross 1 & 2 fused (grid.y = direction) with fp32 final-linear epilogue
    cross_kernel<2,1><<<dim3(BB * N / 32, 2), 256, smem>>>(
        i12, i21, pc1, pc2,
        q1, q2, r1, r2,
        pos1_w, pos1_b, mlp1_w1, mlp1_b1, mlp1_w2, mlp1_b2,
        t1_w, t1_b, t2_w, t2_b,
        f1, f2, out, out + (size_t)BB * 64 * N);

    // cross 3 (1 mlp layer), transposed direct write to output region 2
    cross_kernel<1,0><<<dim3(BB * N / 32, 1), 256, smem>>>(
        i12, i12, pc1, pc2,
        f1, f2, f1, f2,
        pos2_w, pos2_b, mlp2_w1, mlp2_b1, mlp2_w1, mlp2_b1,
        mlp2_w1, mlp2_b1, mlp2_w1, mlp2_b1,
        out + (size_t)2 * BB * 64 * N, out + (size_t)2 * BB * 64 * N,
        out + (size_t)2 * BB * 64 * N, out + (size_t)2 * BB * 64 * N);
}